// round 1
// baseline (speedup 1.0000x reference)
#include <cuda_runtime.h>

#define NN 100000
#define EE 3200000
#define FIN 1433
#define HID 67
#define HP 68          // HID padded to multiple of 4
#define CLS 7

// ---------------- scratch (static device globals; no allocation) ----------------
__device__ int   g_cnt[NN];
__device__ int   g_off[NN + 1];
__device__ int   g_cur[NN];
__device__ int   g_nbr[EE];
__device__ float g_dinv[NN];
__device__ float g_h1[(size_t)NN * HID];   // (x@W1) * dinv[row]
__device__ float g_o1[(size_t)NN * HID];   // leaky_relu(agg1 + b1)
__device__ float g_h2[(size_t)NN * CLS];   // (o1@W2) * dinv[row]

// ---------------- degree counting ----------------
__global__ void k_init() {
    int i = blockIdx.x * blockDim.x + threadIdx.x;
    if (i < NN) g_cnt[i] = 0;
}

__global__ void k_count(const int* __restrict__ col) {
    int e = blockIdx.x * blockDim.x + threadIdx.x;
    if (e < EE) atomicAdd(&g_cnt[col[e]], 1);
}

__global__ void k_dinv() {
    int i = blockIdx.x * blockDim.x + threadIdx.x;
    if (i < NN) g_dinv[i] = rsqrtf((float)(g_cnt[i] + 1));  // +1 self loop
}

// ---------------- exclusive scan of g_cnt -> g_off, g_cur (single block) --------
__global__ void k_scan() {
    __shared__ int wsum[32];
    __shared__ int carry_s;
    int tid = threadIdx.x, lane = tid & 31, wid = tid >> 5;
    if (tid == 0) carry_s = 0;
    __syncthreads();
    for (int base = 0; base < NN; base += 1024) {
        int i = base + tid;
        int v = (i < NN) ? g_cnt[i] : 0;
        int x = v;
        #pragma unroll
        for (int o = 1; o < 32; o <<= 1) {
            int y = __shfl_up_sync(0xffffffffu, x, o);
            if (lane >= o) x += y;
        }
        if (lane == 31) wsum[wid] = x;
        __syncthreads();
        if (wid == 0) {
            int s = wsum[lane];
            #pragma unroll
            for (int o = 1; o < 32; o <<= 1) {
                int y = __shfl_up_sync(0xffffffffu, s, o);
                if (lane >= o) s += y;
            }
            wsum[lane] = s;
        }
        __syncthreads();
        int carry = carry_s;
        int exc = x - v + (wid > 0 ? wsum[wid - 1] : 0);
        if (i < NN) { g_off[i] = carry + exc; g_cur[i] = carry + exc; }
        int tot = wsum[31];
        __syncthreads();
        if (tid == 0) carry_s = carry + tot;
        __syncthreads();
    }
    if (tid == 0) g_off[NN] = carry_s;  // == EE
}

// ---------------- CSR scatter (order within a segment is irrelevant to sums) ----
__global__ void k_scatter(const int* __restrict__ row, const int* __restrict__ col) {
    int e = blockIdx.x * blockDim.x + threadIdx.x;
    if (e < EE) {
        int c = col[e];
        int p = atomicAdd(&g_cur[c], 1);
        g_nbr[p] = row[e];
    }
}

// ---------------- GEMM1: h1 = (x @ W1) * dinv[row] ------------------------------
#define G1_T   128
#define G1_RPB 256   // rows per block (2 per thread)
#define G1_KC  16

__global__ __launch_bounds__(G1_T) void k_gemm1(const float* __restrict__ x,
                                                const float* __restrict__ W1) {
    __shared__ float xs[G1_RPB][G1_KC + 1];            // +1 pad: conflict-free column reads
    __shared__ __align__(16) float ws[G1_KC][HP];      // 68 cols, col 67 zeroed
    int tid = threadIdx.x;
    int row0 = blockIdx.x * G1_RPB;

    float acc0[HP], acc1[HP];
    #pragma unroll
    for (int j = 0; j < HP; j++) { acc0[j] = 0.f; acc1[j] = 0.f; }

    for (int k0 = 0; k0 < FIN; k0 += G1_KC) {
        for (int idx = tid; idx < G1_KC * HP; idx += G1_T) {
            int kk = idx / HP, j = idx % HP;
            int k = k0 + kk;
            ws[kk][j] = (j < HID && k < FIN) ? W1[k * HID + j] : 0.f;
        }
        for (int idx = tid; idx < G1_RPB * G1_KC; idx += G1_T) {
            int r = idx / G1_KC, kk = idx % G1_KC;
            int gr = row0 + r, k = k0 + kk;
            xs[r][kk] = (gr < NN && k < FIN) ? x[(size_t)gr * FIN + k] : 0.f;
        }
        __syncthreads();
        #pragma unroll 4
        for (int kk = 0; kk < G1_KC; kk++) {
            float xv0 = xs[tid][kk];
            float xv1 = xs[tid + G1_T][kk];
            #pragma unroll
            for (int j = 0; j < HP; j += 4) {
                float4 w = *reinterpret_cast<const float4*>(&ws[kk][j]);
                acc0[j]     += xv0 * w.x;
                acc0[j + 1] += xv0 * w.y;
                acc0[j + 2] += xv0 * w.z;
                acc0[j + 3] += xv0 * w.w;
                acc1[j]     += xv1 * w.x;
                acc1[j + 1] += xv1 * w.y;
                acc1[j + 2] += xv1 * w.z;
                acc1[j + 3] += xv1 * w.w;
            }
        }
        __syncthreads();
    }

    int gr0 = row0 + tid, gr1 = row0 + tid + G1_T;
    if (gr0 < NN) {
        float d = g_dinv[gr0];
        #pragma unroll
        for (int j = 0; j < HID; j++) g_h1[(size_t)gr0 * HID + j] = acc0[j] * d;
    }
    if (gr1 < NN) {
        float d = g_dinv[gr1];
        #pragma unroll
        for (int j = 0; j < HID; j++) g_h1[(size_t)gr1 * HID + j] = acc1[j] * d;
    }
}

// ---------------- Aggregation layer 1 (warp per node, lane per feature) ---------
__global__ void k_agg1(const float* __restrict__ b1) {
    int warp = (blockIdx.x * blockDim.x + threadIdx.x) >> 5;
    int lane = threadIdx.x & 31;
    if (warp >= NN) return;
    int c = warp;
    int s = g_off[c], e = g_off[c + 1];
    bool p1 = lane < (HID - 32);  // lane+32 < 67
    bool p2 = lane < (HID - 64);  // lane+64 < 67
    float a0 = 0.f, a1 = 0.f, a2 = 0.f;
    for (int i = s; i < e; i++) {
        int r = g_nbr[i];  // broadcast load
        const float* hr = g_h1 + (size_t)r * HID;
        a0 += hr[lane];
        if (p1) a1 += hr[lane + 32];
        if (p2) a2 += hr[lane + 64];
    }
    const float* hc = g_h1 + (size_t)c * HID;  // self loop (h1 pre-scaled by dinv[c])
    a0 += hc[lane];
    if (p1) a1 += hc[lane + 32];
    if (p2) a2 += hc[lane + 64];

    float d = g_dinv[c];
    float* oc = g_o1 + (size_t)c * HID;
    {
        float v = d * a0 + b1[lane];
        oc[lane] = v > 0.f ? v : 0.01f * v;
    }
    if (p1) {
        float v = d * a1 + b1[lane + 32];
        oc[lane + 32] = v > 0.f ? v : 0.01f * v;
    }
    if (p2) {
        float v = d * a2 + b1[lane + 64];
        oc[lane + 64] = v > 0.f ? v : 0.01f * v;
    }
}

// ---------------- GEMM2: h2 = (o1 @ W2) * dinv[row] -----------------------------
#define G2_T 128
__global__ void k_gemm2(const float* __restrict__ W2) {
    __shared__ float w2s[HID * CLS];
    __shared__ float os[G2_T][HID + 2];  // stride 69: conflict-free
    int tid = threadIdx.x;
    int row0 = blockIdx.x * G2_T;
    for (int idx = tid; idx < HID * CLS; idx += G2_T) w2s[idx] = W2[idx];
    for (int idx = tid; idx < G2_T * HID; idx += G2_T) {
        size_t gidx = (size_t)row0 * HID + idx;
        float v = (gidx < (size_t)NN * HID) ? g_o1[gidx] : 0.f;
        os[idx / HID][idx % HID] = v;
    }
    __syncthreads();
    int gr = row0 + tid;
    if (gr < NN) {
        float acc[CLS];
        #pragma unroll
        for (int j = 0; j < CLS; j++) acc[j] = 0.f;
        for (int k = 0; k < HID; k++) {
            float v = os[tid][k];
            #pragma unroll
            for (int j = 0; j < CLS; j++) acc[j] += v * w2s[k * CLS + j];
        }
        float d = g_dinv[gr];
        #pragma unroll
        for (int j = 0; j < CLS; j++) g_h2[(size_t)gr * CLS + j] = acc[j] * d;
    }
}

// ---------------- Aggregation layer 2 + bias + log_softmax ----------------------
__global__ void k_agg2(const float* __restrict__ b2, float* __restrict__ out) {
    int warp = (blockIdx.x * blockDim.x + threadIdx.x) >> 5;
    int lane = threadIdx.x & 31;
    if (warp >= NN) return;
    int c = warp;
    int s = g_off[c], e = g_off[c + 1];
    float acc[CLS];
    #pragma unroll
    for (int j = 0; j < CLS; j++) acc[j] = 0.f;
    for (int i = s + lane; i < e; i += 32) {
        int r = g_nbr[i];
        const float* hr = g_h2 + (size_t)r * CLS;
        #pragma unroll
        for (int j = 0; j < CLS; j++) acc[j] += hr[j];
    }
    #pragma unroll
    for (int j = 0; j < CLS; j++) {
        #pragma unroll
        for (int o = 16; o > 0; o >>= 1)
            acc[j] += __shfl_xor_sync(0xffffffffu, acc[j], o);
    }
    if (lane == 0) {
        float d = g_dinv[c];
        const float* hc = g_h2 + (size_t)c * CLS;  // self loop
        float v[CLS];
        float m = -1e30f;
        #pragma unroll
        for (int j = 0; j < CLS; j++) {
            v[j] = d * (acc[j] + hc[j]) + b2[j];
            m = fmaxf(m, v[j]);
        }
        float sum = 0.f;
        #pragma unroll
        for (int j = 0; j < CLS; j++) sum += __expf(v[j] - m);
        float lse = m + __logf(sum);
        #pragma unroll
        for (int j = 0; j < CLS; j++) out[(size_t)c * CLS + j] = v[j] - lse;
    }
}

// ---------------- launch --------------------------------------------------------
extern "C" void kernel_launch(void* const* d_in, const int* in_sizes, int n_in,
                              void* d_out, int out_size) {
    const float* x  = (const float*)d_in[0];
    const int*   ei = (const int*)d_in[1];
    const float* W1 = (const float*)d_in[2];
    const float* b1 = (const float*)d_in[3];
    const float* W2 = (const float*)d_in[4];
    const float* b2 = (const float*)d_in[5];
    float* out = (float*)d_out;
    const int* row = ei;        // edge_index[0]
    const int* col = ei + EE;   // edge_index[1]

    k_init<<<(NN + 255) / 256, 256>>>();
    k_count<<<(EE + 255) / 256, 256>>>(col);
    k_scan<<<1, 1024>>>();
    k_dinv<<<(NN + 255) / 256, 256>>>();
    k_scatter<<<(EE + 255) / 256, 256>>>(row, col);
    k_gemm1<<<(NN + G1_RPB - 1) / G1_RPB, G1_T>>>(x, W1);
    {
        long long threads = (long long)NN * 32;
        k_agg1<<<(int)((threads + 255) / 256), 256>>>(b1);
    }
    k_gemm2<<<(NN + G2_T - 1) / G2_T, G2_T>>>(W2);
    {
        long long threads = (long long)NN * 32;
        k_agg2<<<(int)((threads + 255) / 256), 256>>>(b2, out);
    }
}

// round 2
// speedup vs baseline: 1.1983x; 1.1983x over previous
#include <cuda_runtime.h>

#define NN 100000
#define EE 3200000
#define FIN 1433
#define HID 67
#define CLS 7

// ---------------- scratch (static device globals; no allocation) ----------------
__device__ int   g_cnt[NN];
__device__ int   g_off[NN + 1];
__device__ int   g_cur[NN];
__device__ int   g_nbr[EE];
__device__ float g_dinv[NN];
__device__ float g_h1[(size_t)NN * HID];   // (x@W1) * dinv[row]
__device__ float g_o1[(size_t)NN * HID];   // leaky_relu(agg1 + b1)
__device__ float g_h2[(size_t)NN * CLS];   // (o1@W2) * dinv[row]

// ---------------- degree counting ----------------
__global__ void k_init() {
    int i = blockIdx.x * blockDim.x + threadIdx.x;
    if (i < NN) g_cnt[i] = 0;
}

__global__ void k_count(const int* __restrict__ col) {
    int e = blockIdx.x * blockDim.x + threadIdx.x;
    if (e < EE) atomicAdd(&g_cnt[col[e]], 1);
}

__global__ void k_dinv() {
    int i = blockIdx.x * blockDim.x + threadIdx.x;
    if (i < NN) g_dinv[i] = rsqrtf((float)(g_cnt[i] + 1));  // +1 self loop
}

// ---------------- exclusive scan of g_cnt -> g_off, g_cur (single block) --------
__global__ void k_scan() {
    __shared__ int wsum[32];
    __shared__ int carry_s;
    int tid = threadIdx.x, lane = tid & 31, wid = tid >> 5;
    if (tid == 0) carry_s = 0;
    __syncthreads();
    for (int base = 0; base < NN; base += 1024) {
        int i = base + tid;
        int v = (i < NN) ? g_cnt[i] : 0;
        int x = v;
        #pragma unroll
        for (int o = 1; o < 32; o <<= 1) {
            int y = __shfl_up_sync(0xffffffffu, x, o);
            if (lane >= o) x += y;
        }
        if (lane == 31) wsum[wid] = x;
        __syncthreads();
        if (wid == 0) {
            int s = wsum[lane];
            #pragma unroll
            for (int o = 1; o < 32; o <<= 1) {
                int y = __shfl_up_sync(0xffffffffu, s, o);
                if (lane >= o) s += y;
            }
            wsum[lane] = s;
        }
        __syncthreads();
        int carry = carry_s;
        int exc = x - v + (wid > 0 ? wsum[wid - 1] : 0);
        if (i < NN) { g_off[i] = carry + exc; g_cur[i] = carry + exc; }
        int tot = wsum[31];
        __syncthreads();
        if (tid == 0) carry_s = carry + tot;
        __syncthreads();
    }
    if (tid == 0) g_off[NN] = carry_s;  // == EE
}

// ---------------- CSR scatter (order within a segment is irrelevant to sums) ----
__global__ void k_scatter(const int* __restrict__ row, const int* __restrict__ col) {
    int e = blockIdx.x * blockDim.x + threadIdx.x;
    if (e < EE) {
        int c = col[e];
        int p = atomicAdd(&g_cur[c], 1);
        g_nbr[p] = row[e];
    }
}

// ---------------- GEMM1: h1 = (x @ W1) * dinv[row] ------------------------------
// Block: 256 threads = 128 (M) x 2 (N-halves). Thread tile: 2 rows x 36 cols.
// N padded 67 -> 72 so each thread's 36 cols are 9 aligned float4s.
// 72 accumulators/thread -> ~110 regs -> 2 blocks/SM, 16 warps, no spills.
#define G1_T    256
#define G1_RPB  256   // rows per block (2 per thread slot, 128 slots)
#define G1_KC   16
#define NPAD    72
#define CPT     36    // cols per thread
#define CPT4    9     // float4 per thread

__global__ __launch_bounds__(G1_T, 2) void k_gemm1(const float* __restrict__ x,
                                                   const float* __restrict__ W1) {
    __shared__ float xs[G1_RPB][G1_KC + 1];           // +1 pad
    __shared__ __align__(16) float ws[G1_KC][NPAD];   // cols 67..71 zeroed
    int tid = threadIdx.x;
    int tm = tid >> 1;          // 0..127
    int tn = tid & 1;           // 0..1
    int row0 = blockIdx.x * G1_RPB;

    float acc0[CPT], acc1[CPT];
    #pragma unroll
    for (int j = 0; j < CPT; j++) { acc0[j] = 0.f; acc1[j] = 0.f; }

    for (int k0 = 0; k0 < FIN; k0 += G1_KC) {
        // load W chunk (16 x 72 = 1152 floats)
        for (int idx = tid; idx < G1_KC * NPAD; idx += G1_T) {
            int kk = idx / NPAD, j = idx % NPAD;
            int k = k0 + kk;
            ws[kk][j] = (j < HID && k < FIN) ? W1[k * HID + j] : 0.f;
        }
        // load x chunk (256 x 16), coalesced: 16 consecutive tids per row
        for (int idx = tid; idx < G1_RPB * G1_KC; idx += G1_T) {
            int r = idx >> 4, kk = idx & 15;
            int gr = row0 + r, k = k0 + kk;
            xs[r][kk] = (gr < NN && k < FIN) ? x[(size_t)gr * FIN + k] : 0.f;
        }
        __syncthreads();
        #pragma unroll 1
        for (int kk = 0; kk < G1_KC; kk++) {
            float xv0 = xs[tm][kk];
            float xv1 = xs[tm + 128][kk];
            const float4* wrow = reinterpret_cast<const float4*>(&ws[kk][0]) + tn * CPT4;
            #pragma unroll
            for (int j4 = 0; j4 < CPT4; j4++) {
                float4 w = wrow[j4];
                int j = j4 * 4;
                acc0[j]     += xv0 * w.x;
                acc0[j + 1] += xv0 * w.y;
                acc0[j + 2] += xv0 * w.z;
                acc0[j + 3] += xv0 * w.w;
                acc1[j]     += xv1 * w.x;
                acc1[j + 1] += xv1 * w.y;
                acc1[j + 2] += xv1 * w.z;
                acc1[j + 3] += xv1 * w.w;
            }
        }
        __syncthreads();
    }

    int colbase = tn * CPT;
    int gr0 = row0 + tm, gr1 = row0 + tm + 128;
    if (gr0 < NN) {
        float d = g_dinv[gr0];
        #pragma unroll
        for (int j = 0; j < CPT; j++) {
            int c = colbase + j;
            if (c < HID) g_h1[(size_t)gr0 * HID + c] = acc0[j] * d;
        }
    }
    if (gr1 < NN) {
        float d = g_dinv[gr1];
        #pragma unroll
        for (int j = 0; j < CPT; j++) {
            int c = colbase + j;
            if (c < HID) g_h1[(size_t)gr1 * HID + c] = acc1[j] * d;
        }
    }
}

// ---------------- Aggregation layer 1 (warp per node, lane per feature) ---------
__global__ void k_agg1(const float* __restrict__ b1) {
    int warp = (blockIdx.x * blockDim.x + threadIdx.x) >> 5;
    int lane = threadIdx.x & 31;
    if (warp >= NN) return;
    int c = warp;
    int s = g_off[c], e = g_off[c + 1];
    bool p1 = lane < (HID - 32);
    bool p2 = lane < (HID - 64);
    float a0 = 0.f, a1 = 0.f, a2 = 0.f;
    for (int i = s; i < e; i++) {
        int r = g_nbr[i];  // broadcast load
        const float* hr = g_h1 + (size_t)r * HID;
        a0 += hr[lane];
        if (p1) a1 += hr[lane + 32];
        if (p2) a2 += hr[lane + 64];
    }
    const float* hc = g_h1 + (size_t)c * HID;  // self loop (pre-scaled by dinv[c])
    a0 += hc[lane];
    if (p1) a1 += hc[lane + 32];
    if (p2) a2 += hc[lane + 64];

    float d = g_dinv[c];
    float* oc = g_o1 + (size_t)c * HID;
    {
        float v = d * a0 + b1[lane];
        oc[lane] = v > 0.f ? v : 0.01f * v;
    }
    if (p1) {
        float v = d * a1 + b1[lane + 32];
        oc[lane + 32] = v > 0.f ? v : 0.01f * v;
    }
    if (p2) {
        float v = d * a2 + b1[lane + 64];
        oc[lane + 64] = v > 0.f ? v : 0.01f * v;
    }
}

// ---------------- GEMM2: h2 = (o1 @ W2) * dinv[row] -----------------------------
#define G2_T 128
__global__ void k_gemm2(const float* __restrict__ W2) {
    __shared__ float w2s[HID * CLS];
    __shared__ float os[G2_T][HID + 2];
    int tid = threadIdx.x;
    int row0 = blockIdx.x * G2_T;
    for (int idx = tid; idx < HID * CLS; idx += G2_T) w2s[idx] = W2[idx];
    for (int idx = tid; idx < G2_T * HID; idx += G2_T) {
        size_t gidx = (size_t)row0 * HID + idx;
        float v = (gidx < (size_t)NN * HID) ? g_o1[gidx] : 0.f;
        os[idx / HID][idx % HID] = v;
    }
    __syncthreads();
    int gr = row0 + tid;
    if (gr < NN) {
        float acc[CLS];
        #pragma unroll
        for (int j = 0; j < CLS; j++) acc[j] = 0.f;
        for (int k = 0; k < HID; k++) {
            float v = os[tid][k];
            #pragma unroll
            for (int j = 0; j < CLS; j++) acc[j] += v * w2s[k * CLS + j];
        }
        float d = g_dinv[gr];
        #pragma unroll
        for (int j = 0; j < CLS; j++) g_h2[(size_t)gr * CLS + j] = acc[j] * d;
    }
}

// ---------------- Aggregation layer 2 + bias + log_softmax ----------------------
__global__ void k_agg2(const float* __restrict__ b2, float* __restrict__ out) {
    int warp = (blockIdx.x * blockDim.x + threadIdx.x) >> 5;
    int lane = threadIdx.x & 31;
    if (warp >= NN) return;
    int c = warp;
    int s = g_off[c], e = g_off[c + 1];
    float acc[CLS];
    #pragma unroll
    for (int j = 0; j < CLS; j++) acc[j] = 0.f;
    for (int i = s + lane; i < e; i += 32) {
        int r = g_nbr[i];
        const float* hr = g_h2 + (size_t)r * CLS;
        #pragma unroll
        for (int j = 0; j < CLS; j++) acc[j] += hr[j];
    }
    #pragma unroll
    for (int j = 0; j < CLS; j++) {
        #pragma unroll
        for (int o = 16; o > 0; o >>= 1)
            acc[j] += __shfl_xor_sync(0xffffffffu, acc[j], o);
    }
    if (lane == 0) {
        float d = g_dinv[c];
        const float* hc = g_h2 + (size_t)c * CLS;
        float v[CLS];
        float m = -1e30f;
        #pragma unroll
        for (int j = 0; j < CLS; j++) {
            v[j] = d * (acc[j] + hc[j]) + b2[j];
            m = fmaxf(m, v[j]);
        }
        float sum = 0.f;
        #pragma unroll
        for (int j = 0; j < CLS; j++) sum += __expf(v[j] - m);
        float lse = m + __logf(sum);
        #pragma unroll
        for (int j = 0; j < CLS; j++) out[(size_t)c * CLS + j] = v[j] - lse;
    }
}

// ---------------- launch --------------------------------------------------------
extern "C" void kernel_launch(void* const* d_in, const int* in_sizes, int n_in,
                              void* d_out, int out_size) {
    const float* x  = (const float*)d_in[0];
    const int*   ei = (const int*)d_in[1];
    const float* W1 = (const float*)d_in[2];
    const float* b1 = (const float*)d_in[3];
    const float* W2 = (const float*)d_in[4];
    const float* b2 = (const float*)d_in[5];
    float* out = (float*)d_out;
    const int* row = ei;        // edge_index[0]
    const int* col = ei + EE;   // edge_index[1]

    k_init<<<(NN + 255) / 256, 256>>>();
    k_count<<<(EE + 255) / 256, 256>>>(col);
    k_scan<<<1, 1024>>>();
    k_dinv<<<(NN + 255) / 256, 256>>>();
    k_scatter<<<(EE + 255) / 256, 256>>>(row, col);
    k_gemm1<<<(NN + G1_RPB - 1) / G1_RPB, G1_T>>>(x, W1);
    {
        long long threads = (long long)NN * 32;
        k_agg1<<<(int)((threads + 255) / 256), 256>>>(b1);
    }
    k_gemm2<<<(NN + G2_T - 1) / G2_T, G2_T>>>(W2);
    {
        long long threads = (long long)NN * 32;
        k_agg2<<<(int)((threads + 255) / 256), 256>>>(b2, out);
    }
}

// round 6
// speedup vs baseline: 1.3068x; 1.0906x over previous
#include <cuda_runtime.h>

#define NN 100000
#define EE 3200000
#define FIN 1433
#define HID 67
#define CLS 7

// ---------------- scratch (static device globals; no allocation) ----------------
__device__ int   g_cnt[NN];
__device__ int   g_off[NN + 1];
__device__ int   g_cur[NN];
__device__ int   g_nbr[EE];
__device__ float g_dinv[NN];
__device__ float g_h1[(size_t)NN * HID];   // (x@W1) * dinv[row]
__device__ float g_o1[(size_t)NN * HID];   // leaky_relu(agg1 + b1)
__device__ float g_h2[(size_t)NN * CLS];   // (o1@W2) * dinv[row]

// ---------------- degree counting ----------------
__global__ void k_init() {
    int i = blockIdx.x * blockDim.x + threadIdx.x;
    if (i < NN) g_cnt[i] = 0;
}

__global__ void k_count(const int* __restrict__ col) {
    int e = blockIdx.x * blockDim.x + threadIdx.x;
    if (e < EE) atomicAdd(&g_cnt[col[e]], 1);
}

__global__ void k_dinv() {
    int i = blockIdx.x * blockDim.x + threadIdx.x;
    if (i < NN) g_dinv[i] = rsqrtf((float)(g_cnt[i] + 1));  // +1 self loop
}

// ---------------- exclusive scan of g_cnt -> g_off, g_cur (single block) --------
__global__ void k_scan() {
    __shared__ int wsum[32];
    __shared__ int carry_s;
    int tid = threadIdx.x, lane = tid & 31, wid = tid >> 5;
    if (tid == 0) carry_s = 0;
    __syncthreads();
    for (int base = 0; base < NN; base += 1024) {
        int i = base + tid;
        int v = (i < NN) ? g_cnt[i] : 0;
        int x = v;
        #pragma unroll
        for (int o = 1; o < 32; o <<= 1) {
            int y = __shfl_up_sync(0xffffffffu, x, o);
            if (lane >= o) x += y;
        }
        if (lane == 31) wsum[wid] = x;
        __syncthreads();
        if (wid == 0) {
            int s = wsum[lane];
            #pragma unroll
            for (int o = 1; o < 32; o <<= 1) {
                int y = __shfl_up_sync(0xffffffffu, s, o);
                if (lane >= o) s += y;
            }
            wsum[lane] = s;
        }
        __syncthreads();
        int carry = carry_s;
        int exc = x - v + (wid > 0 ? wsum[wid - 1] : 0);
        if (i < NN) { g_off[i] = carry + exc; g_cur[i] = carry + exc; }
        int tot = wsum[31];
        __syncthreads();
        if (tid == 0) carry_s = carry + tot;
        __syncthreads();
    }
    if (tid == 0) g_off[NN] = carry_s;  // == EE
}

// ---------------- CSR scatter (order within a segment is irrelevant to sums) ----
__global__ void k_scatter(const int* __restrict__ row, const int* __restrict__ col) {
    int e = blockIdx.x * blockDim.x + threadIdx.x;
    if (e < EE) {
        int c = col[e];
        int p = atomicAdd(&g_cur[c], 1);
        g_nbr[p] = row[e];
    }
}

// ---------------- GEMM1: h1 = (x @ W1) * dinv[row] ------------------------------
// Block: 256 threads. Thread tile: TM=8 rows x TN=9 cols (72 acc).
// x staged TRANSPOSED: xs[kk][row] (stride 264, 16B aligned) -> 8 x-operands per
// kk-step come from 2 LDS.128. Per kk: 2 LDS.128 + 9 LDS + 72 FFMA
// (~30B smem/FFMA, under the 64B/FFMA crossbar budget -> FFMA-issue bound).
#define G1_T      256
#define G1_RPB    256
#define G1_KC     16
#define XS_STRIDE 264   // multiple of 8 floats -> float4-aligned slices
#define NPAD      72

__global__ __launch_bounds__(G1_T, 2) void k_gemm1(const float* __restrict__ x,
                                                   const float* __restrict__ W1) {
    __shared__ __align__(16) float xs[G1_KC][XS_STRIDE];
    __shared__ float ws[G1_KC][NPAD];
    int tid = threadIdx.x;
    int tn = tid & 7;    // 0..7  -> cols tn*9 .. tn*9+8
    int tm = tid >> 3;   // 0..31 -> rows tm*8 .. tm*8+7
    int row0 = blockIdx.x * G1_RPB;

    float acc[8][9];
    #pragma unroll
    for (int i = 0; i < 8; i++)
        #pragma unroll
        for (int j = 0; j < 9; j++) acc[i][j] = 0.f;

    for (int k0 = 0; k0 < FIN; k0 += G1_KC) {
        // stage W chunk (16 x 72)
        for (int idx = tid; idx < G1_KC * NPAD; idx += G1_T) {
            int kk = idx / NPAD, j = idx % NPAD;
            int k = k0 + kk;
            ws[kk][j] = (j < HID && k < FIN) ? W1[k * HID + j] : 0.f;
        }
        // stage x chunk transposed: consecutive lanes read consecutive k (coalesced)
        for (int idx = tid; idx < G1_RPB * G1_KC; idx += G1_T) {
            int kk = idx & 15, r = idx >> 4;
            int k = k0 + kk, gr = row0 + r;
            xs[kk][r] = (gr < NN && k < FIN) ? x[(size_t)gr * FIN + k] : 0.f;
        }
        __syncthreads();
        #pragma unroll 4
        for (int kk = 0; kk < G1_KC; kk++) {
            float4 xa = *reinterpret_cast<const float4*>(&xs[kk][tm * 8]);
            float4 xb = *reinterpret_cast<const float4*>(&xs[kk][tm * 8 + 4]);
            float xr[8] = {xa.x, xa.y, xa.z, xa.w, xb.x, xb.y, xb.z, xb.w};
            float wv[9];
            #pragma unroll
            for (int j = 0; j < 9; j++) wv[j] = ws[kk][tn * 9 + j];
            #pragma unroll
            for (int i = 0; i < 8; i++)
                #pragma unroll
                for (int j = 0; j < 9; j++)
                    acc[i][j] += xr[i] * wv[j];
        }
        __syncthreads();
    }

    #pragma unroll
    for (int i = 0; i < 8; i++) {
        int gr = row0 + tm * 8 + i;
        if (gr < NN) {
            float d = g_dinv[gr];
            #pragma unroll
            for (int j = 0; j < 9; j++) {
                int c = tn * 9 + j;
                if (c < HID) g_h1[(size_t)gr * HID + c] = acc[i][j] * d;
            }
        }
    }
}

// ---------------- Aggregation layer 1 (warp per node, lane per feature) ---------
__global__ void k_agg1(const float* __restrict__ b1) {
    int warp = (blockIdx.x * blockDim.x + threadIdx.x) >> 5;
    int lane = threadIdx.x & 31;
    if (warp >= NN) return;
    int c = warp;
    int s = g_off[c], e = g_off[c + 1];
    bool p1 = lane < (HID - 32);
    bool p2 = lane < (HID - 64);
    float a0 = 0.f, a1 = 0.f, a2 = 0.f;
    for (int i = s; i < e; i++) {
        int r = g_nbr[i];  // broadcast load
        const float* hr = g_h1 + (size_t)r * HID;
        a0 += hr[lane];
        if (p1) a1 += hr[lane + 32];
        if (p2) a2 += hr[lane + 64];
    }
    const float* hc = g_h1 + (size_t)c * HID;  // self loop (pre-scaled by dinv[c])
    a0 += hc[lane];
    if (p1) a1 += hc[lane + 32];
    if (p2) a2 += hc[lane + 64];

    float d = g_dinv[c];
    float* oc = g_o1 + (size_t)c * HID;
    {
        float v = d * a0 + b1[lane];
        oc[lane] = v > 0.f ? v : 0.01f * v;
    }
    if (p1) {
        float v = d * a1 + b1[lane + 32];
        oc[lane + 32] = v > 0.f ? v : 0.01f * v;
    }
    if (p2) {
        float v = d * a2 + b1[lane + 64];
        oc[lane + 64] = v > 0.f ? v : 0.01f * v;
    }
}

// ---------------- GEMM2: h2 = (o1 @ W2) * dinv[row] -----------------------------
#define G2_T 128
__global__ void k_gemm2(const float* __restrict__ W2) {
    __shared__ float w2s[HID * CLS];
    __shared__ float os[G2_T][HID + 2];
    int tid = threadIdx.x;
    int row0 = blockIdx.x * G2_T;
    for (int idx = tid; idx < HID * CLS; idx += G2_T) w2s[idx] = W2[idx];
    for (int idx = tid; idx < G2_T * HID; idx += G2_T) {
        size_t gidx = (size_t)row0 * HID + idx;
        float v = (gidx < (size_t)NN * HID) ? g_o1[gidx] : 0.f;
        os[idx / HID][idx % HID] = v;
    }
    __syncthreads();
    int gr = row0 + tid;
    if (gr < NN) {
        float acc[CLS];
        #pragma unroll
        for (int j = 0; j < CLS; j++) acc[j] = 0.f;
        for (int k = 0; k < HID; k++) {
            float v = os[tid][k];
            #pragma unroll
            for (int j = 0; j < CLS; j++) acc[j] += v * w2s[k * CLS + j];
        }
        float d = g_dinv[gr];
        #pragma unroll
        for (int j = 0; j < CLS; j++) g_h2[(size_t)gr * CLS + j] = acc[j] * d;
    }
}

// ---------------- Aggregation layer 2 + bias + log_softmax ----------------------
__global__ void k_agg2(const float* __restrict__ b2, float* __restrict__ out) {
    int warp = (blockIdx.x * blockDim.x + threadIdx.x) >> 5;
    int lane = threadIdx.x & 31;
    if (warp >= NN) return;
    int c = warp;
    int s = g_off[c], e = g_off[c + 1];
    float acc[CLS];
    #pragma unroll
    for (int j = 0; j < CLS; j++) acc[j] = 0.f;
    for (int i = s + lane; i < e; i += 32) {
        int r = g_nbr[i];
        const float* hr = g_h2 + (size_t)r * CLS;
        #pragma unroll
        for (int j = 0; j < CLS; j++) acc[j] += hr[j];
    }
    #pragma unroll
    for (int j = 0; j < CLS; j++) {
        #pragma unroll
        for (int o = 16; o > 0; o >>= 1)
            acc[j] += __shfl_xor_sync(0xffffffffu, acc[j], o);
    }
    if (lane == 0) {
        float d = g_dinv[c];
        const float* hc = g_h2 + (size_t)c * CLS;
        float v[CLS];
        float m = -1e30f;
        #pragma unroll
        for (int j = 0; j < CLS; j++) {
            v[j] = d * (acc[j] + hc[j]) + b2[j];
            m = fmaxf(m, v[j]);
        }
        float sum = 0.f;
        #pragma unroll
        for (int j = 0; j < CLS; j++) sum += __expf(v[j] - m);
        float lse = m + __logf(sum);
        #pragma unroll
        for (int j = 0; j < CLS; j++) out[(size_t)c * CLS + j] = v[j] - lse;
    }
}

// ---------------- launch --------------------------------------------------------
// Order puts k_gemm1 at the launch index the ncu window captures (4th launch).
// Dependencies preserved: dinv needs count; gemm1 needs dinv; scan needs count
// (g_cnt untouched by dinv); scatter needs scan; agg1 needs gemm1 + scatter.
extern "C" void kernel_launch(void* const* d_in, const int* in_sizes, int n_in,
                              void* d_out, int out_size) {
    const float* x  = (const float*)d_in[0];
    const int*   ei = (const int*)d_in[1];
    const float* W1 = (const float*)d_in[2];
    const float* b1 = (const float*)d_in[3];
    const float* W2 = (const float*)d_in[4];
    const float* b2 = (const float*)d_in[5];
    float* out = (float*)d_out;
    const int* row = ei;        // edge_index[0]
    const int* col = ei + EE;   // edge_index[1]

    k_init<<<(NN + 255) / 256, 256>>>();
    k_count<<<(EE + 255) / 256, 256>>>(col);
    k_dinv<<<(NN + 255) / 256, 256>>>();
    k_gemm1<<<(NN + G1_RPB - 1) / G1_RPB, G1_T>>>(x, W1);
    k_scan<<<1, 1024>>>();
    k_scatter<<<(EE + 255) / 256, 256>>>(row, col);
    {
        long long threads = (long long)NN * 32;
        k_agg1<<<(int)((threads + 255) / 256), 256>>>(b1);
    }
    k_gemm2<<<(NN + G2_T - 1) / G2_T, G2_T>>>(W2);
    {
        long long threads = (long long)NN * 32;
        k_agg2<<<(int)((threads + 255) / 256), 256>>>(b2, out);
    }
}

// round 7
// speedup vs baseline: 1.9728x; 1.5096x over previous
#include <cuda_runtime.h>

#define NN 100000
#define EE 3200000
#define FIN 1433
#define HID 67
#define CLS 7

typedef unsigned long long u64;

// ---------------- scratch (static device globals; no allocation) ----------------
__device__ int   g_cnt[NN];
__device__ int   g_off[NN + 1];
__device__ int   g_cur[NN];
__device__ int   g_nbr[EE];
__device__ float g_dinv[NN];
__device__ float g_h1[(size_t)NN * HID];   // (x@W1) * dinv[row]
__device__ float g_o1[(size_t)NN * HID];   // leaky_relu(agg1 + b1)
__device__ float g_h2[(size_t)NN * CLS];   // (o1@W2) * dinv[row]

// ---------------- degree counting ----------------
__global__ void k_init() {
    int i = blockIdx.x * blockDim.x + threadIdx.x;
    if (i < NN) g_cnt[i] = 0;
}

__global__ void k_count(const int* __restrict__ col) {
    int e = blockIdx.x * blockDim.x + threadIdx.x;
    if (e < EE) atomicAdd(&g_cnt[col[e]], 1);
}

__global__ void k_dinv() {
    int i = blockIdx.x * blockDim.x + threadIdx.x;
    if (i < NN) g_dinv[i] = rsqrtf((float)(g_cnt[i] + 1));  // +1 self loop
}

// ---------------- exclusive scan of g_cnt -> g_off, g_cur (single block) --------
__global__ void k_scan() {
    __shared__ int wsum[32];
    __shared__ int carry_s;
    int tid = threadIdx.x, lane = tid & 31, wid = tid >> 5;
    if (tid == 0) carry_s = 0;
    __syncthreads();
    for (int base = 0; base < NN; base += 1024) {
        int i = base + tid;
        int v = (i < NN) ? g_cnt[i] : 0;
        int x = v;
        #pragma unroll
        for (int o = 1; o < 32; o <<= 1) {
            int y = __shfl_up_sync(0xffffffffu, x, o);
            if (lane >= o) x += y;
        }
        if (lane == 31) wsum[wid] = x;
        __syncthreads();
        if (wid == 0) {
            int s = wsum[lane];
            #pragma unroll
            for (int o = 1; o < 32; o <<= 1) {
                int y = __shfl_up_sync(0xffffffffu, s, o);
                if (lane >= o) s += y;
            }
            wsum[lane] = s;
        }
        __syncthreads();
        int carry = carry_s;
        int exc = x - v + (wid > 0 ? wsum[wid - 1] : 0);
        if (i < NN) { g_off[i] = carry + exc; g_cur[i] = carry + exc; }
        int tot = wsum[31];
        __syncthreads();
        if (tid == 0) carry_s = carry + tot;
        __syncthreads();
    }
    if (tid == 0) g_off[NN] = carry_s;  // == EE
}

// ---------------- CSR scatter (order within a segment is irrelevant to sums) ----
__global__ void k_scatter(const int* __restrict__ row, const int* __restrict__ col) {
    int e = blockIdx.x * blockDim.x + threadIdx.x;
    if (e < EE) {
        int c = col[e];
        int p = atomicAdd(&g_cur[c], 1);
        g_nbr[p] = row[e];
    }
}

// ---------------- GEMM1: h1 = (x @ W1) * dinv[row] ------------------------------
// 256 threads; thread tile TM=8 rows x TN=9 cols, rows packed in f32x2 pairs:
// 36 fma.rn.f32x2 per kk (vs 72 FFMA). W staged PRE-DUPLICATED as float2 in smem
// (LDS.64 gives a ready packed operand). Global->shared staging is register
// double-buffered: prefetch chunk c+1 into regs while computing chunk c.
#define G1_T      256
#define G1_RPB    256
#define G1_KC     16
#define XS_STRIDE 264   // floats; multiple of 8 -> 16B-aligned 8-row slices
#define NPAD      72
#define NCHUNK    ((FIN + G1_KC - 1) / G1_KC)   // 90
#define PX        16    // x prefetch regs per thread (256*16/256)
#define PW        5     // w prefetch regs per thread (ceil(16*72/256))

__device__ __forceinline__ void fma2(u64& d, u64 a, u64 b) {
    asm("fma.rn.f32x2 %0, %1, %2, %0;" : "+l"(d) : "l"(a), "l"(b));
}

__global__ __launch_bounds__(G1_T, 2) void k_gemm1(const float* __restrict__ x,
                                                   const float* __restrict__ W1) {
    __shared__ __align__(16) float xs[G1_KC][XS_STRIDE];
    __shared__ __align__(16) float2 ws2[G1_KC][NPAD];   // (w, w) duplicated
    int tid = threadIdx.x;
    int tn = tid & 7;    // 0..7  -> cols tn*9 .. tn*9+8
    int tm = tid >> 3;   // 0..31 -> rows tm*8 .. tm*8+7
    int row0 = blockIdx.x * G1_RPB;

    u64 acc[4][9];       // row-pairs (2i,2i+1) x 9 cols, packed f32x2
    #pragma unroll
    for (int i = 0; i < 4; i++)
        #pragma unroll
        for (int j = 0; j < 9; j++) acc[i][j] = 0ULL;

    float px[PX];
    float pw[PW];

    // ---- prefetch + stage chunk 0 ----
    {
        int k0 = 0;
        #pragma unroll
        for (int t = 0; t < PX; t++) {
            int idx = tid + t * G1_T;
            int kk = idx & 15, r = idx >> 4;
            int k = k0 + kk, gr = row0 + r;
            px[t] = (gr < NN && k < FIN) ? x[(size_t)gr * FIN + k] : 0.f;
        }
        #pragma unroll
        for (int t = 0; t < PW; t++) {
            int idx = tid + t * G1_T;
            if (idx < G1_KC * NPAD) {
                int kk = idx / NPAD, j = idx % NPAD;
                int k = k0 + kk;
                pw[t] = (j < HID && k < FIN) ? W1[k * HID + j] : 0.f;
            }
        }
        #pragma unroll
        for (int t = 0; t < PX; t++) {
            int idx = tid + t * G1_T;
            xs[idx & 15][idx >> 4] = px[t];
        }
        #pragma unroll
        for (int t = 0; t < PW; t++) {
            int idx = tid + t * G1_T;
            if (idx < G1_KC * NPAD) {
                int kk = idx / NPAD, j = idx % NPAD;
                ws2[kk][j] = make_float2(pw[t], pw[t]);
            }
        }
        __syncthreads();
    }

    for (int c = 0; c < NCHUNK; c++) {
        // prefetch chunk c+1 into regs (LDG issues early, hidden by compute)
        if (c + 1 < NCHUNK) {
            int k0 = (c + 1) * G1_KC;
            #pragma unroll
            for (int t = 0; t < PX; t++) {
                int idx = tid + t * G1_T;
                int kk = idx & 15, r = idx >> 4;
                int k = k0 + kk, gr = row0 + r;
                px[t] = (gr < NN && k < FIN) ? x[(size_t)gr * FIN + k] : 0.f;
            }
            #pragma unroll
            for (int t = 0; t < PW; t++) {
                int idx = tid + t * G1_T;
                if (idx < G1_KC * NPAD) {
                    int kk = idx / NPAD, j = idx % NPAD;
                    int k = k0 + kk;
                    pw[t] = (j < HID && k < FIN) ? W1[k * HID + j] : 0.f;
                }
            }
        }

        // compute current chunk
        #pragma unroll 4
        for (int kk = 0; kk < G1_KC; kk++) {
            ulonglong2 xA = *reinterpret_cast<const ulonglong2*>(&xs[kk][tm * 8]);
            ulonglong2 xB = *reinterpret_cast<const ulonglong2*>(&xs[kk][tm * 8 + 4]);
            u64 xp[4] = {xA.x, xA.y, xB.x, xB.y};   // rows (0,1)(2,3)(4,5)(6,7)
            #pragma unroll
            for (int j = 0; j < 9; j++) {
                u64 w2 = *reinterpret_cast<const u64*>(&ws2[kk][tn * 9 + j]);
                fma2(acc[0][j], xp[0], w2);
                fma2(acc[1][j], xp[1], w2);
                fma2(acc[2][j], xp[2], w2);
                fma2(acc[3][j], xp[3], w2);
            }
        }
        __syncthreads();   // everyone done reading current buffer

        if (c + 1 < NCHUNK) {
            #pragma unroll
            for (int t = 0; t < PX; t++) {
                int idx = tid + t * G1_T;
                xs[idx & 15][idx >> 4] = px[t];
            }
            #pragma unroll
            for (int t = 0; t < PW; t++) {
                int idx = tid + t * G1_T;
                if (idx < G1_KC * NPAD) {
                    int kk = idx / NPAD, j = idx % NPAD;
                    ws2[kk][j] = make_float2(pw[t], pw[t]);
                }
            }
            __syncthreads();
        }
    }

    // epilogue: unpack pairs, scale by dinv, store
    #pragma unroll
    for (int i = 0; i < 4; i++) {
        int gr0 = row0 + tm * 8 + 2 * i;
        int gr1 = gr0 + 1;
        float d0 = (gr0 < NN) ? g_dinv[gr0] : 0.f;
        float d1 = (gr1 < NN) ? g_dinv[gr1] : 0.f;
        #pragma unroll
        for (int j = 0; j < 9; j++) {
            int cidx = tn * 9 + j;
            float2 v = *reinterpret_cast<const float2*>(&acc[i][j]);
            if (cidx < HID) {
                if (gr0 < NN) g_h1[(size_t)gr0 * HID + cidx] = v.x * d0;
                if (gr1 < NN) g_h1[(size_t)gr1 * HID + cidx] = v.y * d1;
            }
        }
    }
}

// ---------------- Aggregation layer 1 (warp per node, lane per feature) ---------
__global__ void k_agg1(const float* __restrict__ b1) {
    int warp = (blockIdx.x * blockDim.x + threadIdx.x) >> 5;
    int lane = threadIdx.x & 31;
    if (warp >= NN) return;
    int c = warp;
    int s = g_off[c], e = g_off[c + 1];
    bool p1 = lane < (HID - 32);
    bool p2 = lane < (HID - 64);
    float a0 = 0.f, a1 = 0.f, a2 = 0.f;
    for (int i = s; i < e; i++) {
        int r = g_nbr[i];  // broadcast load
        const float* hr = g_h1 + (size_t)r * HID;
        a0 += hr[lane];
        if (p1) a1 += hr[lane + 32];
        if (p2) a2 += hr[lane + 64];
    }
    const float* hc = g_h1 + (size_t)c * HID;  // self loop (pre-scaled by dinv[c])
    a0 += hc[lane];
    if (p1) a1 += hc[lane + 32];
    if (p2) a2 += hc[lane + 64];

    float d = g_dinv[c];
    float* oc = g_o1 + (size_t)c * HID;
    {
        float v = d * a0 + b1[lane];
        oc[lane] = v > 0.f ? v : 0.01f * v;
    }
    if (p1) {
        float v = d * a1 + b1[lane + 32];
        oc[lane + 32] = v > 0.f ? v : 0.01f * v;
    }
    if (p2) {
        float v = d * a2 + b1[lane + 64];
        oc[lane + 64] = v > 0.f ? v : 0.01f * v;
    }
}

// ---------------- GEMM2: h2 = (o1 @ W2) * dinv[row] -----------------------------
#define G2_T 128
__global__ void k_gemm2(const float* __restrict__ W2) {
    __shared__ float w2s[HID * CLS];
    __shared__ float os[G2_T][HID + 2];
    int tid = threadIdx.x;
    int row0 = blockIdx.x * G2_T;
    for (int idx = tid; idx < HID * CLS; idx += G2_T) w2s[idx] = W2[idx];
    for (int idx = tid; idx < G2_T * HID; idx += G2_T) {
        size_t gidx = (size_t)row0 * HID + idx;
        float v = (gidx < (size_t)NN * HID) ? g_o1[gidx] : 0.f;
        os[idx / HID][idx % HID] = v;
    }
    __syncthreads();
    int gr = row0 + tid;
    if (gr < NN) {
        float acc[CLS];
        #pragma unroll
        for (int j = 0; j < CLS; j++) acc[j] = 0.f;
        for (int k = 0; k < HID; k++) {
            float v = os[tid][k];
            #pragma unroll
            for (int j = 0; j < CLS; j++) acc[j] += v * w2s[k * CLS + j];
        }
        float d = g_dinv[gr];
        #pragma unroll
        for (int j = 0; j < CLS; j++) g_h2[(size_t)gr * CLS + j] = acc[j] * d;
    }
}

// ---------------- Aggregation layer 2 + bias + log_softmax ----------------------
__global__ void k_agg2(const float* __restrict__ b2, float* __restrict__ out) {
    int warp = (blockIdx.x * blockDim.x + threadIdx.x) >> 5;
    int lane = threadIdx.x & 31;
    if (warp >= NN) return;
    int c = warp;
    int s = g_off[c], e = g_off[c + 1];
    float acc[CLS];
    #pragma unroll
    for (int j = 0; j < CLS; j++) acc[j] = 0.f;
    for (int i = s + lane; i < e; i += 32) {
        int r = g_nbr[i];
        const float* hr = g_h2 + (size_t)r * CLS;
        #pragma unroll
        for (int j = 0; j < CLS; j++) acc[j] += hr[j];
    }
    #pragma unroll
    for (int j = 0; j < CLS; j++) {
        #pragma unroll
        for (int o = 16; o > 0; o >>= 1)
            acc[j] += __shfl_xor_sync(0xffffffffu, acc[j], o);
    }
    if (lane == 0) {
        float d = g_dinv[c];
        const float* hc = g_h2 + (size_t)c * CLS;
        float v[CLS];
        float m = -1e30f;
        #pragma unroll
        for (int j = 0; j < CLS; j++) {
            v[j] = d * (acc[j] + hc[j]) + b2[j];
            m = fmaxf(m, v[j]);
        }
        float sum = 0.f;
        #pragma unroll
        for (int j = 0; j < CLS; j++) sum += __expf(v[j] - m);
        float lse = m + __logf(sum);
        #pragma unroll
        for (int j = 0; j < CLS; j++) out[(size_t)c * CLS + j] = v[j] - lse;
    }
}

// ---------------- launch --------------------------------------------------------
// k_gemm1 stays the 4th launch (ncu capture window). Dependencies preserved.
extern "C" void kernel_launch(void* const* d_in, const int* in_sizes, int n_in,
                              void* d_out, int out_size) {
    const float* x  = (const float*)d_in[0];
    const int*   ei = (const int*)d_in[1];
    const float* W1 = (const float*)d_in[2];
    const float* b1 = (const float*)d_in[3];
    const float* W2 = (const float*)d_in[4];
    const float* b2 = (const float*)d_in[5];
    float* out = (float*)d_out;
    const int* row = ei;        // edge_index[0]
    const int* col = ei + EE;   // edge_index[1]

    k_init<<<(NN + 255) / 256, 256>>>();
    k_count<<<(EE + 255) / 256, 256>>>(col);
    k_dinv<<<(NN + 255) / 256, 256>>>();
    k_gemm1<<<(NN + G1_RPB - 1) / G1_RPB, G1_T>>>(x, W1);
    k_scan<<<1, 1024>>>();
    k_scatter<<<(EE + 255) / 256, 256>>>(row, col);
    {
        long long threads = (long long)NN * 32;
        k_agg1<<<(int)((threads + 255) / 256), 256>>>(b1);
    }
    k_gemm2<<<(NN + G2_T - 1) / G2_T, G2_T>>>(W2);
    {
        long long threads = (long long)NN * 32;
        k_agg2<<<(int)((threads + 255) / 256), 256>>>(b2, out);
    }
}

// round 9
// speedup vs baseline: 2.6814x; 1.3592x over previous
#include <cuda_runtime.h>
#include <cstdint>

#define NN 100000
#define EE 3200000
#define FIN 1433
#define HID 67
#define CLS 7

typedef unsigned long long u64;

// ---------------- scratch (static device globals; no allocation) ----------------
__device__ int   g_cnt[NN];
__device__ int   g_off[NN + 1];
__device__ int   g_cur[NN];
__device__ int   g_nbr[EE];
__device__ float g_dinv[NN];
__device__ float g_h1[(size_t)NN * HID];   // (x@W1) * dinv[row]
__device__ float g_o1[(size_t)NN * HID];   // leaky_relu(agg1 + b1)
__device__ float g_h2[(size_t)NN * CLS];   // (o1@W2) * dinv[row]

// ---------------- degree counting ----------------
__global__ void k_init() {
    int i = blockIdx.x * blockDim.x + threadIdx.x;
    if (i < NN) g_cnt[i] = 0;
}

__global__ void k_count(const int* __restrict__ col) {
    int e = blockIdx.x * blockDim.x + threadIdx.x;
    if (e < EE) atomicAdd(&g_cnt[col[e]], 1);
}

__global__ void k_dinv() {
    int i = blockIdx.x * blockDim.x + threadIdx.x;
    if (i < NN) g_dinv[i] = rsqrtf((float)(g_cnt[i] + 1));  // +1 self loop
}

// ---------------- exclusive scan of g_cnt -> g_off, g_cur (single block) --------
__global__ void k_scan() {
    __shared__ int wsum[32];
    __shared__ int carry_s;
    int tid = threadIdx.x, lane = tid & 31, wid = tid >> 5;
    if (tid == 0) carry_s = 0;
    __syncthreads();
    for (int base = 0; base < NN; base += 1024) {
        int i = base + tid;
        int v = (i < NN) ? g_cnt[i] : 0;
        int x = v;
        #pragma unroll
        for (int o = 1; o < 32; o <<= 1) {
            int y = __shfl_up_sync(0xffffffffu, x, o);
            if (lane >= o) x += y;
        }
        if (lane == 31) wsum[wid] = x;
        __syncthreads();
        if (wid == 0) {
            int s = wsum[lane];
            #pragma unroll
            for (int o = 1; o < 32; o <<= 1) {
                int y = __shfl_up_sync(0xffffffffu, s, o);
                if (lane >= o) s += y;
            }
            wsum[lane] = s;
        }
        __syncthreads();
        int carry = carry_s;
        int exc = x - v + (wid > 0 ? wsum[wid - 1] : 0);
        if (i < NN) { g_off[i] = carry + exc; g_cur[i] = carry + exc; }
        int tot = wsum[31];
        __syncthreads();
        if (tid == 0) carry_s = carry + tot;
        __syncthreads();
    }
    if (tid == 0) g_off[NN] = carry_s;  // == EE
}

// ---------------- CSR scatter ----------------------------------------------------
__global__ void k_scatter(const int* __restrict__ row, const int* __restrict__ col) {
    int e = blockIdx.x * blockDim.x + threadIdx.x;
    if (e < EE) {
        int c = col[e];
        int p = atomicAdd(&g_cur[c], 1);
        g_nbr[p] = row[e];
    }
}

// ---------------- GEMM1 (warp-MMA tf32): h1 = (x @ W1) * dinv[row] ---------------
// mma.sync.aligned.m16n8k8 tf32 (base-sm_103 legal; runs on tensor pipe as HMMA).
// CTA: 128 thr / 4 warps. Tile M=128 x N=72, K-chunk 16 (2 k8-steps).
// Warp w owns rows w*32..w*32+31 (2 m16-tiles) x all 9 n8-tiles -> 18 mma/k8.
// A/B staged tf32-rounded with k-interleave (cols k,k+4 adjacent) so each
// fragment load is one LDS.64; stride 40 floats -> conflict-free (4r+c pattern).
#define G1_T     128
#define G1_M     128
#define G1_NP    72
#define G1_KC    16
#define G1_NCH   ((FIN + G1_KC - 1) / G1_KC)   // 90
#define AS_STR   40
#define BS_STR   40
#define PXN      16   // 128*16/128
#define PWN      9    // 72*16/128

__device__ __forceinline__ int kpos(int kk) {
    int s = kk >> 3, t = kk & 7;
    return s * 8 + ((t < 4) ? (2 * t) : (2 * (t - 4) + 1));
}

__device__ __forceinline__ uint32_t tf32(float v) {
    uint32_t u;
    asm("cvt.rna.tf32.f32 %0, %1;" : "=r"(u) : "f"(v));
    return u;
}

__device__ __forceinline__ void mma_tf32(float* d, const uint32_t* a,
                                         uint32_t b0, uint32_t b1) {
    asm volatile(
        "mma.sync.aligned.m16n8k8.row.col.f32.tf32.tf32.f32 "
        "{%0,%1,%2,%3}, {%4,%5,%6,%7}, {%8,%9}, {%0,%1,%2,%3};"
        : "+f"(d[0]), "+f"(d[1]), "+f"(d[2]), "+f"(d[3])
        : "r"(a[0]), "r"(a[1]), "r"(a[2]), "r"(a[3]), "r"(b0), "r"(b1));
}

__global__ __launch_bounds__(G1_T) void k_gemm1(const float* __restrict__ x,
                                                const float* __restrict__ W1) {
    __shared__ __align__(16) float As[G1_M][AS_STR];
    __shared__ __align__(16) float Bs[G1_NP][BS_STR];
    int tid = threadIdx.x;
    int lane = tid & 31, w = tid >> 5;
    int g = lane >> 2, t = lane & 3;
    int row0 = blockIdx.x * G1_M;
    int wrow = w * 32;

    float acc[2][9][4];
    #pragma unroll
    for (int mt = 0; mt < 2; mt++)
        #pragma unroll
        for (int nt = 0; nt < 9; nt++)
            #pragma unroll
            for (int q = 0; q < 4; q++) acc[mt][nt][q] = 0.f;

    float px[PXN];
    float pw[PWN];

    // ---- stage chunk 0 ----
    {
        int k0 = 0;
        #pragma unroll
        for (int i = 0; i < PXN; i++) {
            int idx = tid + i * G1_T;
            int kk = idx & 15, r = idx >> 4;
            int gr = row0 + r, k = k0 + kk;
            px[i] = (gr < NN && k < FIN) ? x[(size_t)gr * FIN + k] : 0.f;
        }
        #pragma unroll
        for (int i = 0; i < PWN; i++) {
            int idx = tid + i * G1_T;
            int n = idx % G1_NP, kk = idx / G1_NP;
            int k = k0 + kk;
            pw[i] = (n < HID && k < FIN) ? W1[k * HID + n] : 0.f;
        }
        #pragma unroll
        for (int i = 0; i < PXN; i++) {
            int idx = tid + i * G1_T;
            int kk = idx & 15, r = idx >> 4;
            As[r][kpos(kk)] = __uint_as_float(tf32(px[i]));
        }
        #pragma unroll
        for (int i = 0; i < PWN; i++) {
            int idx = tid + i * G1_T;
            int n = idx % G1_NP, kk = idx / G1_NP;
            Bs[n][kpos(kk)] = __uint_as_float(tf32(pw[i]));
        }
        __syncthreads();
    }

    for (int c = 0; c < G1_NCH; c++) {
        // prefetch chunk c+1 into regs
        if (c + 1 < G1_NCH) {
            int k0 = (c + 1) * G1_KC;
            #pragma unroll
            for (int i = 0; i < PXN; i++) {
                int idx = tid + i * G1_T;
                int kk = idx & 15, r = idx >> 4;
                int gr = row0 + r, k = k0 + kk;
                px[i] = (gr < NN && k < FIN) ? x[(size_t)gr * FIN + k] : 0.f;
            }
            #pragma unroll
            for (int i = 0; i < PWN; i++) {
                int idx = tid + i * G1_T;
                int n = idx % G1_NP, kk = idx / G1_NP;
                int k = k0 + kk;
                pw[i] = (n < HID && k < FIN) ? W1[k * HID + n] : 0.f;
            }
        }

        // compute: 2 k8-steps
        #pragma unroll
        for (int s = 0; s < 2; s++) {
            uint32_t af[2][4];
            #pragma unroll
            for (int mt = 0; mt < 2; mt++) {
                float2 lo = *reinterpret_cast<const float2*>(
                    &As[wrow + mt * 16 + g][s * 8 + 2 * t]);
                float2 hi = *reinterpret_cast<const float2*>(
                    &As[wrow + mt * 16 + 8 + g][s * 8 + 2 * t]);
                af[mt][0] = __float_as_uint(lo.x);   // a0: row g,   col t
                af[mt][1] = __float_as_uint(hi.x);   // a1: row g+8, col t
                af[mt][2] = __float_as_uint(lo.y);   // a2: row g,   col t+4
                af[mt][3] = __float_as_uint(hi.y);   // a3: row g+8, col t+4
            }
            #pragma unroll
            for (int nt = 0; nt < 9; nt++) {
                float2 bf = *reinterpret_cast<const float2*>(
                    &Bs[nt * 8 + g][s * 8 + 2 * t]);
                uint32_t b0 = __float_as_uint(bf.x);  // k=t,   n=g
                uint32_t b1 = __float_as_uint(bf.y);  // k=t+4, n=g
                mma_tf32(acc[0][nt], af[0], b0, b1);
                mma_tf32(acc[1][nt], af[1], b0, b1);
            }
        }
        __syncthreads();

        if (c + 1 < G1_NCH) {
            #pragma unroll
            for (int i = 0; i < PXN; i++) {
                int idx = tid + i * G1_T;
                int kk = idx & 15, r = idx >> 4;
                As[r][kpos(kk)] = __uint_as_float(tf32(px[i]));
            }
            #pragma unroll
            for (int i = 0; i < PWN; i++) {
                int idx = tid + i * G1_T;
                int n = idx % G1_NP, kk = idx / G1_NP;
                Bs[n][kpos(kk)] = __uint_as_float(tf32(pw[i]));
            }
            __syncthreads();
        }
    }

    // epilogue: c0(row g,col 2t) c1(row g,col 2t+1) c2(row g+8,2t) c3(row g+8,2t+1)
    #pragma unroll
    for (int mt = 0; mt < 2; mt++) {
        int r0 = row0 + wrow + mt * 16 + g;
        int r1 = r0 + 8;
        float d0 = (r0 < NN) ? g_dinv[r0] : 0.f;
        float d1 = (r1 < NN) ? g_dinv[r1] : 0.f;
        #pragma unroll
        for (int nt = 0; nt < 9; nt++) {
            int col = nt * 8 + 2 * t;
            if (col < HID) {
                if (r0 < NN) g_h1[(size_t)r0 * HID + col] = acc[mt][nt][0] * d0;
                if (r1 < NN) g_h1[(size_t)r1 * HID + col] = acc[mt][nt][2] * d1;
            }
            if (col + 1 < HID) {
                if (r0 < NN) g_h1[(size_t)r0 * HID + col + 1] = acc[mt][nt][1] * d0;
                if (r1 < NN) g_h1[(size_t)r1 * HID + col + 1] = acc[mt][nt][3] * d1;
            }
        }
    }
}

// ---------------- Aggregation layer 1 (warp per node, lane per feature) ---------
__global__ void k_agg1(const float* __restrict__ b1) {
    int warp = (blockIdx.x * blockDim.x + threadIdx.x) >> 5;
    int lane = threadIdx.x & 31;
    if (warp >= NN) return;
    int c = warp;
    int s = g_off[c], e = g_off[c + 1];
    bool p1 = lane < (HID - 32);
    bool p2 = lane < (HID - 64);
    float a0 = 0.f, a1 = 0.f, a2 = 0.f;
    for (int i = s; i < e; i++) {
        int r = g_nbr[i];  // broadcast load
        const float* hr = g_h1 + (size_t)r * HID;
        a0 += hr[lane];
        if (p1) a1 += hr[lane + 32];
        if (p2) a2 += hr[lane + 64];
    }
    const float* hc = g_h1 + (size_t)c * HID;  // self loop (pre-scaled by dinv[c])
    a0 += hc[lane];
    if (p1) a1 += hc[lane + 32];
    if (p2) a2 += hc[lane + 64];

    float d = g_dinv[c];
    float* oc = g_o1 + (size_t)c * HID;
    {
        float v = d * a0 + b1[lane];
        oc[lane] = v > 0.f ? v : 0.01f * v;
    }
    if (p1) {
        float v = d * a1 + b1[lane + 32];
        oc[lane + 32] = v > 0.f ? v : 0.01f * v;
    }
    if (p2) {
        float v = d * a2 + b1[lane + 64];
        oc[lane + 64] = v > 0.f ? v : 0.01f * v;
    }
}

// ---------------- GEMM2: h2 = (o1 @ W2) * dinv[row] -----------------------------
#define G2_T 128
__global__ void k_gemm2(const float* __restrict__ W2) {
    __shared__ float w2s[HID * CLS];
    __shared__ float os[G2_T][HID + 2];
    int tid = threadIdx.x;
    int row0 = blockIdx.x * G2_T;
    for (int idx = tid; idx < HID * CLS; idx += G2_T) w2s[idx] = W2[idx];
    for (int idx = tid; idx < G2_T * HID; idx += G2_T) {
        size_t gidx = (size_t)row0 * HID + idx;
        float v = (gidx < (size_t)NN * HID) ? g_o1[gidx] : 0.f;
        os[idx / HID][idx % HID] = v;
    }
    __syncthreads();
    int gr = row0 + tid;
    if (gr < NN) {
        float acc[CLS];
        #pragma unroll
        for (int j = 0; j < CLS; j++) acc[j] = 0.f;
        for (int k = 0; k < HID; k++) {
            float v = os[tid][k];
            #pragma unroll
            for (int j = 0; j < CLS; j++) acc[j] += v * w2s[k * CLS + j];
        }
        float d = g_dinv[gr];
        #pragma unroll
        for (int j = 0; j < CLS; j++) g_h2[(size_t)gr * CLS + j] = acc[j] * d;
    }
}

// ---------------- Aggregation layer 2 + bias + log_softmax ----------------------
__global__ void k_agg2(const float* __restrict__ b2, float* __restrict__ out) {
    int warp = (blockIdx.x * blockDim.x + threadIdx.x) >> 5;
    int lane = threadIdx.x & 31;
    if (warp >= NN) return;
    int c = warp;
    int s = g_off[c], e = g_off[c + 1];
    float acc[CLS];
    #pragma unroll
    for (int j = 0; j < CLS; j++) acc[j] = 0.f;
    for (int i = s + lane; i < e; i += 32) {
        int r = g_nbr[i];
        const float* hr = g_h2 + (size_t)r * CLS;
        #pragma unroll
        for (int j = 0; j < CLS; j++) acc[j] += hr[j];
    }
    #pragma unroll
    for (int j = 0; j < CLS; j++) {
        #pragma unroll
        for (int o = 16; o > 0; o >>= 1)
            acc[j] += __shfl_xor_sync(0xffffffffu, acc[j], o);
    }
    if (lane == 0) {
        float d = g_dinv[c];
        const float* hc = g_h2 + (size_t)c * CLS;
        float v[CLS];
        float m = -1e30f;
        #pragma unroll
        for (int j = 0; j < CLS; j++) {
            v[j] = d * (acc[j] + hc[j]) + b2[j];
            m = fmaxf(m, v[j]);
        }
        float sum = 0.f;
        #pragma unroll
        for (int j = 0; j < CLS; j++) sum += __expf(v[j] - m);
        float lse = m + __logf(sum);
        #pragma unroll
        for (int j = 0; j < CLS; j++) out[(size_t)c * CLS + j] = v[j] - lse;
    }
}

// ---------------- launch --------------------------------------------------------
// k_gemm1 stays the 4th launch (ncu capture window). Dependencies preserved.
extern "C" void kernel_launch(void* const* d_in, const int* in_sizes, int n_in,
                              void* d_out, int out_size) {
    const float* x  = (const float*)d_in[0];
    const int*   ei = (const int*)d_in[1];
    const float* W1 = (const float*)d_in[2];
    const float* b1 = (const float*)d_in[3];
    const float* W2 = (const float*)d_in[4];
    const float* b2 = (const float*)d_in[5];
    float* out = (float*)d_out;
    const int* row = ei;        // edge_index[0]
    const int* col = ei + EE;   // edge_index[1]

    k_init<<<(NN + 255) / 256, 256>>>();
    k_count<<<(EE + 255) / 256, 256>>>(col);
    k_dinv<<<(NN + 255) / 256, 256>>>();
    k_gemm1<<<(NN + G1_M - 1) / G1_M, G1_T>>>(x, W1);
    k_scan<<<1, 1024>>>();
    k_scatter<<<(EE + 255) / 256, 256>>>(row, col);
    {
        long long threads = (long long)NN * 32;
        k_agg1<<<(int)((threads + 255) / 256), 256>>>(b1);
    }
    k_gemm2<<<(NN + G2_T - 1) / G2_T, G2_T>>>(W2);
    {
        long long threads = (long long)NN * 32;
        k_agg2<<<(int)((threads + 255) / 256), 256>>>(b2, out);
    }
}

// round 10
// speedup vs baseline: 2.8592x; 1.0663x over previous
#include <cuda_runtime.h>
#include <cstdint>

#define NN 100000
#define EE 3200000
#define FIN 1433
#define HID 67
#define CLS 7

typedef unsigned long long u64;

// ---------------- scratch (static device globals; no allocation) ----------------
__device__ int   g_cnt[NN];
__device__ int   g_off[NN + 1];
__device__ int   g_cur[NN];
__device__ int   g_nbr[EE];
__device__ float g_dinv[NN];
__device__ float g_h1[(size_t)NN * HID];   // (x@W1) * dinv[row]
__device__ float g_o1[(size_t)NN * HID];   // leaky_relu(agg1 + b1)
__device__ float g_h2[(size_t)NN * CLS];   // (o1@W2) * dinv[row]

// ---------------- degree counting ----------------
__global__ void k_init() {
    int i = blockIdx.x * blockDim.x + threadIdx.x;
    if (i < NN) g_cnt[i] = 0;
}

__global__ void k_count(const int* __restrict__ col) {
    int e = blockIdx.x * blockDim.x + threadIdx.x;
    if (e < EE) atomicAdd(&g_cnt[col[e]], 1);
}

__global__ void k_dinv() {
    int i = blockIdx.x * blockDim.x + threadIdx.x;
    if (i < NN) g_dinv[i] = rsqrtf((float)(g_cnt[i] + 1));  // +1 self loop
}

// ---------------- exclusive scan of g_cnt -> g_off, g_cur (single block) --------
__global__ void k_scan() {
    __shared__ int wsum[32];
    __shared__ int carry_s;
    int tid = threadIdx.x, lane = tid & 31, wid = tid >> 5;
    if (tid == 0) carry_s = 0;
    __syncthreads();
    for (int base = 0; base < NN; base += 1024) {
        int i = base + tid;
        int v = (i < NN) ? g_cnt[i] : 0;
        int x = v;
        #pragma unroll
        for (int o = 1; o < 32; o <<= 1) {
            int y = __shfl_up_sync(0xffffffffu, x, o);
            if (lane >= o) x += y;
        }
        if (lane == 31) wsum[wid] = x;
        __syncthreads();
        if (wid == 0) {
            int s = wsum[lane];
            #pragma unroll
            for (int o = 1; o < 32; o <<= 1) {
                int y = __shfl_up_sync(0xffffffffu, s, o);
                if (lane >= o) s += y;
            }
            wsum[lane] = s;
        }
        __syncthreads();
        int carry = carry_s;
        int exc = x - v + (wid > 0 ? wsum[wid - 1] : 0);
        if (i < NN) { g_off[i] = carry + exc; g_cur[i] = carry + exc; }
        int tot = wsum[31];
        __syncthreads();
        if (tid == 0) carry_s = carry + tot;
        __syncthreads();
    }
    if (tid == 0) g_off[NN] = carry_s;  // == EE
}

// ---------------- CSR scatter ----------------------------------------------------
__global__ void k_scatter(const int* __restrict__ row, const int* __restrict__ col) {
    int e = blockIdx.x * blockDim.x + threadIdx.x;
    if (e < EE) {
        int c = col[e];
        int p = atomicAdd(&g_cur[c], 1);
        g_nbr[p] = row[e];
    }
}

// ---------------- GEMM1 (warp-MMA tf32): h1 = (x @ W1) * dinv[row] ---------------
// mma.sync.m16n8k8 tf32. CTA: 256 thr / 8 warps. Tile M=128 x N=72.
// Warp w owns rows w*16..w*16+15 (ONE m16-tile) x 9 n8-tiles -> acc = 36 regs.
// K-chunk 16 (2 k8-steps); register double-buffered staging (8+5 regs).
// Goal vs R9: regs 206 -> ~95 so 2 CTAs/SM (16 warps) hide LDS/LDG latency.
#define G1_T     256
#define G1_M     128
#define G1_NP    72
#define G1_KC    16
#define G1_NCH   ((FIN + G1_KC - 1) / G1_KC)   // 90
#define AS_STR   24
#define BS_STR   24
#define PXN      8    // 128*16/256
#define PWN      5    // ceil(72*16/256)

__device__ __forceinline__ int kpos(int kk) {
    int s = kk >> 3, t = kk & 7;
    return s * 8 + ((t < 4) ? (2 * t) : (2 * (t - 4) + 1));
}

__device__ __forceinline__ uint32_t tf32(float v) {
    uint32_t u;
    asm("cvt.rna.tf32.f32 %0, %1;" : "=r"(u) : "f"(v));
    return u;
}

__device__ __forceinline__ void mma_tf32(float* d, const uint32_t* a,
                                         uint32_t b0, uint32_t b1) {
    asm volatile(
        "mma.sync.aligned.m16n8k8.row.col.f32.tf32.tf32.f32 "
        "{%0,%1,%2,%3}, {%4,%5,%6,%7}, {%8,%9}, {%0,%1,%2,%3};"
        : "+f"(d[0]), "+f"(d[1]), "+f"(d[2]), "+f"(d[3])
        : "r"(a[0]), "r"(a[1]), "r"(a[2]), "r"(a[3]), "r"(b0), "r"(b1));
}

__global__ __launch_bounds__(G1_T, 2) void k_gemm1(const float* __restrict__ x,
                                                   const float* __restrict__ W1) {
    __shared__ __align__(16) float As[G1_M][AS_STR];
    __shared__ __align__(16) float Bs[G1_NP][BS_STR];
    int tid = threadIdx.x;
    int lane = tid & 31, w = tid >> 5;
    int g = lane >> 2, t = lane & 3;
    int row0 = blockIdx.x * G1_M;
    int wrow = w * 16;

    float acc[9][4];
    #pragma unroll
    for (int nt = 0; nt < 9; nt++)
        #pragma unroll
        for (int q = 0; q < 4; q++) acc[nt][q] = 0.f;

    float px[PXN];
    float pw[PWN];

    // ---- stage chunk 0 ----
    {
        int k0 = 0;
        #pragma unroll
        for (int i = 0; i < PXN; i++) {
            int idx = tid + i * G1_T;
            int kk = idx & 15, r = idx >> 4;
            int gr = row0 + r, k = k0 + kk;
            px[i] = (gr < NN && k < FIN) ? x[(size_t)gr * FIN + k] : 0.f;
        }
        #pragma unroll
        for (int i = 0; i < PWN; i++) {
            int idx = tid + i * G1_T;
            if (idx < G1_NP * G1_KC) {
                int n = idx % G1_NP, kk = idx / G1_NP;
                int k = k0 + kk;
                pw[i] = (n < HID && k < FIN) ? W1[k * HID + n] : 0.f;
            }
        }
        #pragma unroll
        for (int i = 0; i < PXN; i++) {
            int idx = tid + i * G1_T;
            As[idx >> 4][kpos(idx & 15)] = __uint_as_float(tf32(px[i]));
        }
        #pragma unroll
        for (int i = 0; i < PWN; i++) {
            int idx = tid + i * G1_T;
            if (idx < G1_NP * G1_KC) {
                int n = idx % G1_NP, kk = idx / G1_NP;
                Bs[n][kpos(kk)] = __uint_as_float(tf32(pw[i]));
            }
        }
        __syncthreads();
    }

    for (int c = 0; c < G1_NCH; c++) {
        // prefetch chunk c+1 into regs
        if (c + 1 < G1_NCH) {
            int k0 = (c + 1) * G1_KC;
            #pragma unroll
            for (int i = 0; i < PXN; i++) {
                int idx = tid + i * G1_T;
                int kk = idx & 15, r = idx >> 4;
                int gr = row0 + r, k = k0 + kk;
                px[i] = (gr < NN && k < FIN) ? x[(size_t)gr * FIN + k] : 0.f;
            }
            #pragma unroll
            for (int i = 0; i < PWN; i++) {
                int idx = tid + i * G1_T;
                if (idx < G1_NP * G1_KC) {
                    int n = idx % G1_NP, kk = idx / G1_NP;
                    int k = k0 + kk;
                    pw[i] = (n < HID && k < FIN) ? W1[k * HID + n] : 0.f;
                }
            }
        }

        // compute: 2 k8-steps, 9 MMAs each
        #pragma unroll
        for (int s = 0; s < 2; s++) {
            uint32_t af[4];
            {
                float2 lo = *reinterpret_cast<const float2*>(
                    &As[wrow + g][s * 8 + 2 * t]);
                float2 hi = *reinterpret_cast<const float2*>(
                    &As[wrow + 8 + g][s * 8 + 2 * t]);
                af[0] = __float_as_uint(lo.x);
                af[1] = __float_as_uint(hi.x);
                af[2] = __float_as_uint(lo.y);
                af[3] = __float_as_uint(hi.y);
            }
            #pragma unroll
            for (int nt = 0; nt < 9; nt++) {
                float2 bf = *reinterpret_cast<const float2*>(
                    &Bs[nt * 8 + g][s * 8 + 2 * t]);
                mma_tf32(acc[nt], af, __float_as_uint(bf.x), __float_as_uint(bf.y));
            }
        }
        __syncthreads();

        if (c + 1 < G1_NCH) {
            #pragma unroll
            for (int i = 0; i < PXN; i++) {
                int idx = tid + i * G1_T;
                As[idx >> 4][kpos(idx & 15)] = __uint_as_float(tf32(px[i]));
            }
            #pragma unroll
            for (int i = 0; i < PWN; i++) {
                int idx = tid + i * G1_T;
                if (idx < G1_NP * G1_KC) {
                    int n = idx % G1_NP, kk = idx / G1_NP;
                    Bs[n][kpos(kk)] = __uint_as_float(tf32(pw[i]));
                }
            }
            __syncthreads();
        }
    }

    // epilogue: c0(row g,col 2t) c1(row g,2t+1) c2(row g+8,2t) c3(row g+8,2t+1)
    int r0 = row0 + wrow + g;
    int r1 = r0 + 8;
    float d0 = (r0 < NN) ? g_dinv[r0] : 0.f;
    float d1 = (r1 < NN) ? g_dinv[r1] : 0.f;
    #pragma unroll
    for (int nt = 0; nt < 9; nt++) {
        int col = nt * 8 + 2 * t;
        if (col < HID) {
            if (r0 < NN) g_h1[(size_t)r0 * HID + col] = acc[nt][0] * d0;
            if (r1 < NN) g_h1[(size_t)r1 * HID + col] = acc[nt][2] * d1;
        }
        if (col + 1 < HID) {
            if (r0 < NN) g_h1[(size_t)r0 * HID + col + 1] = acc[nt][1] * d0;
            if (r1 < NN) g_h1[(size_t)r1 * HID + col + 1] = acc[nt][3] * d1;
        }
    }
}

// ---------------- Aggregation layer 1 (warp per node, lane per feature) ---------
__global__ void k_agg1(const float* __restrict__ b1) {
    int warp = (blockIdx.x * blockDim.x + threadIdx.x) >> 5;
    int lane = threadIdx.x & 31;
    if (warp >= NN) return;
    int c = warp;
    int s = g_off[c], e = g_off[c + 1];
    bool p1 = lane < (HID - 32);
    bool p2 = lane < (HID - 64);
    float a0 = 0.f, a1 = 0.f, a2 = 0.f;
    for (int i = s; i < e; i++) {
        int r = g_nbr[i];  // broadcast load
        const float* hr = g_h1 + (size_t)r * HID;
        a0 += hr[lane];
        if (p1) a1 += hr[lane + 32];
        if (p2) a2 += hr[lane + 64];
    }
    const float* hc = g_h1 + (size_t)c * HID;  // self loop (pre-scaled by dinv[c])
    a0 += hc[lane];
    if (p1) a1 += hc[lane + 32];
    if (p2) a2 += hc[lane + 64];

    float d = g_dinv[c];
    float* oc = g_o1 + (size_t)c * HID;
    {
        float v = d * a0 + b1[lane];
        oc[lane] = v > 0.f ? v : 0.01f * v;
    }
    if (p1) {
        float v = d * a1 + b1[lane + 32];
        oc[lane + 32] = v > 0.f ? v : 0.01f * v;
    }
    if (p2) {
        float v = d * a2 + b1[lane + 64];
        oc[lane + 64] = v > 0.f ? v : 0.01f * v;
    }
}

// ---------------- GEMM2: h2 = (o1 @ W2) * dinv[row] -----------------------------
#define G2_T 128
__global__ void k_gemm2(const float* __restrict__ W2) {
    __shared__ float w2s[HID * CLS];
    __shared__ float os[G2_T][HID + 2];
    int tid = threadIdx.x;
    int row0 = blockIdx.x * G2_T;
    for (int idx = tid; idx < HID * CLS; idx += G2_T) w2s[idx] = W2[idx];
    for (int idx = tid; idx < G2_T * HID; idx += G2_T) {
        size_t gidx = (size_t)row0 * HID + idx;
        float v = (gidx < (size_t)NN * HID) ? g_o1[gidx] : 0.f;
        os[idx / HID][idx % HID] = v;
    }
    __syncthreads();
    int gr = row0 + tid;
    if (gr < NN) {
        float acc[CLS];
        #pragma unroll
        for (int j = 0; j < CLS; j++) acc[j] = 0.f;
        for (int k = 0; k < HID; k++) {
            float v = os[tid][k];
            #pragma unroll
            for (int j = 0; j < CLS; j++) acc[j] += v * w2s[k * CLS + j];
        }
        float d = g_dinv[gr];
        #pragma unroll
        for (int j = 0; j < CLS; j++) g_h2[(size_t)gr * CLS + j] = acc[j] * d;
    }
}

// ---------------- Aggregation layer 2 + bias + log_softmax ----------------------
__global__ void k_agg2(const float* __restrict__ b2, float* __restrict__ out) {
    int warp = (blockIdx.x * blockDim.x + threadIdx.x) >> 5;
    int lane = threadIdx.x & 31;
    if (warp >= NN) return;
    int c = warp;
    int s = g_off[c], e = g_off[c + 1];
    float acc[CLS];
    #pragma unroll
    for (int j = 0; j < CLS; j++) acc[j] = 0.f;
    for (int i = s + lane; i < e; i += 32) {
        int r = g_nbr[i];
        const float* hr = g_h2 + (size_t)r * CLS;
        #pragma unroll
        for (int j = 0; j < CLS; j++) acc[j] += hr[j];
    }
    #pragma unroll
    for (int j = 0; j < CLS; j++) {
        #pragma unroll
        for (int o = 16; o > 0; o >>= 1)
            acc[j] += __shfl_xor_sync(0xffffffffu, acc[j], o);
    }
    if (lane == 0) {
        float d = g_dinv[c];
        const float* hc = g_h2 + (size_t)c * CLS;
        float v[CLS];
        float m = -1e30f;
        #pragma unroll
        for (int j = 0; j < CLS; j++) {
            v[j] = d * (acc[j] + hc[j]) + b2[j];
            m = fmaxf(m, v[j]);
        }
        float sum = 0.f;
        #pragma unroll
        for (int j = 0; j < CLS; j++) sum += __expf(v[j] - m);
        float lse = m + __logf(sum);
        #pragma unroll
        for (int j = 0; j < CLS; j++) out[(size_t)c * CLS + j] = v[j] - lse;
    }
}

// ---------------- launch --------------------------------------------------------
// k_gemm1 stays the 4th launch (ncu capture window). Dependencies preserved.
extern "C" void kernel_launch(void* const* d_in, const int* in_sizes, int n_in,
                              void* d_out, int out_size) {
    const float* x  = (const float*)d_in[0];
    const int*   ei = (const int*)d_in[1];
    const float* W1 = (const float*)d_in[2];
    const float* b1 = (const float*)d_in[3];
    const float* W2 = (const float*)d_in[4];
    const float* b2 = (const float*)d_in[5];
    float* out = (float*)d_out;
    const int* row = ei;        // edge_index[0]
    const int* col = ei + EE;   // edge_index[1]

    k_init<<<(NN + 255) / 256, 256>>>();
    k_count<<<(EE + 255) / 256, 256>>>(col);
    k_dinv<<<(NN + 255) / 256, 256>>>();
    k_gemm1<<<(NN + G1_M - 1) / G1_M, G1_T>>>(x, W1);
    k_scan<<<1, 1024>>>();
    k_scatter<<<(EE + 255) / 256, 256>>>(row, col);
    {
        long long threads = (long long)NN * 32;
        k_agg1<<<(int)((threads + 255) / 256), 256>>>(b1);
    }
    k_gemm2<<<(NN + G2_T - 1) / G2_T, G2_T>>>(W2);
    {
        long long threads = (long long)NN * 32;
        k_agg2<<<(int)((threads + 255) / 256), 256>>>(b2, out);
    }
}

// round 11
// speedup vs baseline: 3.0822x; 1.0780x over previous
#include <cuda_runtime.h>
#include <cstdint>

#define NN 100000
#define EE 3200000
#define FIN 1433
#define HID 67
#define CLS 7

typedef unsigned long long u64;

// ---------------- scratch (static device globals; no allocation) ----------------
__device__ int   g_cnt[NN];
__device__ int   g_off[NN + 1];
__device__ int   g_cur[NN];
__device__ int   g_nbr[EE];
__device__ float g_dinv[NN];
__device__ float g_h1[(size_t)NN * HID];   // (x@W1) * dinv[row]
__device__ float g_o1[(size_t)NN * HID];   // leaky_relu(agg1 + b1)
__device__ float g_h2[(size_t)NN * CLS];   // (o1@W2) * dinv[row]

// ---------------- degree counting ----------------
__global__ void k_init() {
    int i = blockIdx.x * blockDim.x + threadIdx.x;
    if (i < NN) g_cnt[i] = 0;
}

__global__ void k_count(const int* __restrict__ col) {
    int e = blockIdx.x * blockDim.x + threadIdx.x;
    if (e < EE) atomicAdd(&g_cnt[col[e]], 1);
}

__global__ void k_dinv() {
    int i = blockIdx.x * blockDim.x + threadIdx.x;
    if (i < NN) g_dinv[i] = rsqrtf((float)(g_cnt[i] + 1));  // +1 self loop
}

// ---------------- exclusive scan of g_cnt -> g_off, g_cur (single block) --------
__global__ void k_scan() {
    __shared__ int wsum[32];
    __shared__ int carry_s;
    int tid = threadIdx.x, lane = tid & 31, wid = tid >> 5;
    if (tid == 0) carry_s = 0;
    __syncthreads();
    for (int base = 0; base < NN; base += 1024) {
        int i = base + tid;
        int v = (i < NN) ? g_cnt[i] : 0;
        int x = v;
        #pragma unroll
        for (int o = 1; o < 32; o <<= 1) {
            int y = __shfl_up_sync(0xffffffffu, x, o);
            if (lane >= o) x += y;
        }
        if (lane == 31) wsum[wid] = x;
        __syncthreads();
        if (wid == 0) {
            int s = wsum[lane];
            #pragma unroll
            for (int o = 1; o < 32; o <<= 1) {
                int y = __shfl_up_sync(0xffffffffu, s, o);
                if (lane >= o) s += y;
            }
            wsum[lane] = s;
        }
        __syncthreads();
        int carry = carry_s;
        int exc = x - v + (wid > 0 ? wsum[wid - 1] : 0);
        if (i < NN) { g_off[i] = carry + exc; g_cur[i] = carry + exc; }
        int tot = wsum[31];
        __syncthreads();
        if (tid == 0) carry_s = carry + tot;
        __syncthreads();
    }
    if (tid == 0) g_off[NN] = carry_s;  // == EE
}

// ---------------- CSR scatter ----------------------------------------------------
__global__ void k_scatter(const int* __restrict__ row, const int* __restrict__ col) {
    int e = blockIdx.x * blockDim.x + threadIdx.x;
    if (e < EE) {
        int c = col[e];
        int p = atomicAdd(&g_cur[c], 1);
        g_nbr[p] = row[e];
    }
}

// ---------------- GEMM1 (warp-MMA tf32): h1 = (x @ W1) * dinv[row] ---------------
// mma.sync.m16n8k8 tf32. CTA: 256 thr / 8 warps. Tile M=128 x N=72; warp owns
// one m16-tile x 9 n8-tiles (acc 36 regs). K-chunk 16, register prefetch.
// R11: PING-PONG smem buffers -> ONE barrier per chunk (90 vs 180) and
// __launch_bounds__(256,3) -> 24 warps/SM for latency cover.
#define G1_T     256
#define G1_M     128
#define G1_NP    72
#define G1_KC    16
#define G1_NCH   ((FIN + G1_KC - 1) / G1_KC)   // 90
#define AS_STR   24
#define BS_STR   24
#define PXN      8    // 128*16/256
#define PWN      5    // ceil(72*16/256)

__device__ __forceinline__ int kpos(int kk) {
    int s = kk >> 3, t = kk & 7;
    return s * 8 + ((t < 4) ? (2 * t) : (2 * (t - 4) + 1));
}

__device__ __forceinline__ uint32_t tf32(float v) {
    uint32_t u;
    asm("cvt.rna.tf32.f32 %0, %1;" : "=r"(u) : "f"(v));
    return u;
}

__device__ __forceinline__ void mma_tf32(float* d, const uint32_t* a,
                                         uint32_t b0, uint32_t b1) {
    asm volatile(
        "mma.sync.aligned.m16n8k8.row.col.f32.tf32.tf32.f32 "
        "{%0,%1,%2,%3}, {%4,%5,%6,%7}, {%8,%9}, {%0,%1,%2,%3};"
        : "+f"(d[0]), "+f"(d[1]), "+f"(d[2]), "+f"(d[3])
        : "r"(a[0]), "r"(a[1]), "r"(a[2]), "r"(a[3]), "r"(b0), "r"(b1));
}

__global__ __launch_bounds__(G1_T, 3) void k_gemm1(const float* __restrict__ x,
                                                   const float* __restrict__ W1) {
    __shared__ __align__(16) float As[2][G1_M][AS_STR];
    __shared__ __align__(16) float Bs[2][G1_NP][BS_STR];
    int tid = threadIdx.x;
    int lane = tid & 31, w = tid >> 5;
    int g = lane >> 2, t = lane & 3;
    int row0 = blockIdx.x * G1_M;
    int wrow = w * 16;

    float acc[9][4];
    #pragma unroll
    for (int nt = 0; nt < 9; nt++)
        #pragma unroll
        for (int q = 0; q < 4; q++) acc[nt][q] = 0.f;

    float px[PXN];
    float pw[PWN];

    // precomputed staging indices (loop-invariant)
    int xi_kk[PXN], xi_r[PXN];
    #pragma unroll
    for (int i = 0; i < PXN; i++) {
        int idx = tid + i * G1_T;
        xi_kk[i] = idx & 15;
        xi_r[i] = idx >> 4;
    }
    int wi_n[PWN], wi_kk[PWN];
    bool wi_ok[PWN];
    #pragma unroll
    for (int i = 0; i < PWN; i++) {
        int idx = tid + i * G1_T;
        wi_ok[i] = idx < G1_NP * G1_KC;
        wi_n[i] = idx % G1_NP;
        wi_kk[i] = idx / G1_NP;
    }

    // ---- stage chunk 0 into buffer 0 ----
    {
        #pragma unroll
        for (int i = 0; i < PXN; i++) {
            int gr = row0 + xi_r[i], k = xi_kk[i];
            px[i] = (gr < NN) ? x[(size_t)gr * FIN + k] : 0.f;
        }
        #pragma unroll
        for (int i = 0; i < PWN; i++) {
            pw[i] = 0.f;
            if (wi_ok[i] && wi_n[i] < HID)
                pw[i] = W1[wi_kk[i] * HID + wi_n[i]];
        }
        #pragma unroll
        for (int i = 0; i < PXN; i++)
            As[0][xi_r[i]][kpos(xi_kk[i])] = __uint_as_float(tf32(px[i]));
        #pragma unroll
        for (int i = 0; i < PWN; i++)
            if (wi_ok[i]) Bs[0][wi_n[i]][kpos(wi_kk[i])] = __uint_as_float(tf32(pw[i]));
        __syncthreads();
    }

    for (int c = 0; c < G1_NCH; c++) {
        int buf = c & 1;
        // prefetch chunk c+1 into regs
        if (c + 1 < G1_NCH) {
            int k0 = (c + 1) * G1_KC;
            #pragma unroll
            for (int i = 0; i < PXN; i++) {
                int gr = row0 + xi_r[i], k = k0 + xi_kk[i];
                px[i] = (gr < NN && k < FIN) ? x[(size_t)gr * FIN + k] : 0.f;
            }
            #pragma unroll
            for (int i = 0; i < PWN; i++) {
                pw[i] = 0.f;
                if (wi_ok[i]) {
                    int k = k0 + wi_kk[i];
                    if (wi_n[i] < HID && k < FIN) pw[i] = W1[k * HID + wi_n[i]];
                }
            }
        }

        // compute: 2 k8-steps, 9 MMAs each
        #pragma unroll
        for (int s = 0; s < 2; s++) {
            uint32_t af[4];
            {
                float2 lo = *reinterpret_cast<const float2*>(
                    &As[buf][wrow + g][s * 8 + 2 * t]);
                float2 hi = *reinterpret_cast<const float2*>(
                    &As[buf][wrow + 8 + g][s * 8 + 2 * t]);
                af[0] = __float_as_uint(lo.x);
                af[1] = __float_as_uint(hi.x);
                af[2] = __float_as_uint(lo.y);
                af[3] = __float_as_uint(hi.y);
            }
            #pragma unroll
            for (int nt = 0; nt < 9; nt++) {
                float2 bf = *reinterpret_cast<const float2*>(
                    &Bs[buf][nt * 8 + g][s * 8 + 2 * t]);
                mma_tf32(acc[nt], af, __float_as_uint(bf.x), __float_as_uint(bf.y));
            }
        }

        // stage chunk c+1 into the OTHER buffer (no read hazard), then one barrier
        if (c + 1 < G1_NCH) {
            int nb = buf ^ 1;
            #pragma unroll
            for (int i = 0; i < PXN; i++)
                As[nb][xi_r[i]][kpos(xi_kk[i])] = __uint_as_float(tf32(px[i]));
            #pragma unroll
            for (int i = 0; i < PWN; i++)
                if (wi_ok[i]) Bs[nb][wi_n[i]][kpos(wi_kk[i])] = __uint_as_float(tf32(pw[i]));
            __syncthreads();
        }
    }

    // epilogue: c0(row g,col 2t) c1(row g,2t+1) c2(row g+8,2t) c3(row g+8,2t+1)
    int r0 = row0 + wrow + g;
    int r1 = r0 + 8;
    float d0 = (r0 < NN) ? g_dinv[r0] : 0.f;
    float d1 = (r1 < NN) ? g_dinv[r1] : 0.f;
    #pragma unroll
    for (int nt = 0; nt < 9; nt++) {
        int col = nt * 8 + 2 * t;
        if (col < HID) {
            if (r0 < NN) g_h1[(size_t)r0 * HID + col] = acc[nt][0] * d0;
            if (r1 < NN) g_h1[(size_t)r1 * HID + col] = acc[nt][2] * d1;
        }
        if (col + 1 < HID) {
            if (r0 < NN) g_h1[(size_t)r0 * HID + col + 1] = acc[nt][1] * d0;
            if (r1 < NN) g_h1[(size_t)r1 * HID + col + 1] = acc[nt][3] * d1;
        }
    }
}

// ---------------- Aggregation layer 1 (warp per node, lane per feature) ---------
__global__ void k_agg1(const float* __restrict__ b1) {
    int warp = (blockIdx.x * blockDim.x + threadIdx.x) >> 5;
    int lane = threadIdx.x & 31;
    if (warp >= NN) return;
    int c = warp;
    int s = g_off[c], e = g_off[c + 1];
    bool p1 = lane < (HID - 32);
    bool p2 = lane < (HID - 64);
    float a0 = 0.f, a1 = 0.f, a2 = 0.f;
    for (int i = s; i < e; i++) {
        int r = g_nbr[i];  // broadcast load
        const float* hr = g_h1 + (size_t)r * HID;
        a0 += hr[lane];
        if (p1) a1 += hr[lane + 32];
        if (p2) a2 += hr[lane + 64];
    }
    const float* hc = g_h1 + (size_t)c * HID;  // self loop (pre-scaled by dinv[c])
    a0 += hc[lane];
    if (p1) a1 += hc[lane + 32];
    if (p2) a2 += hc[lane + 64];

    float d = g_dinv[c];
    float* oc = g_o1 + (size_t)c * HID;
    {
        float v = d * a0 + b1[lane];
        oc[lane] = v > 0.f ? v : 0.01f * v;
    }
    if (p1) {
        float v = d * a1 + b1[lane + 32];
        oc[lane + 32] = v > 0.f ? v : 0.01f * v;
    }
    if (p2) {
        float v = d * a2 + b1[lane + 64];
        oc[lane + 64] = v > 0.f ? v : 0.01f * v;
    }
}

// ---------------- GEMM2: h2 = (o1 @ W2) * dinv[row] -----------------------------
#define G2_T 128
__global__ void k_gemm2(const float* __restrict__ W2) {
    __shared__ float w2s[HID * CLS];
    __shared__ float os[G2_T][HID + 2];
    int tid = threadIdx.x;
    int row0 = blockIdx.x * G2_T;
    for (int idx = tid; idx < HID * CLS; idx += G2_T) w2s[idx] = W2[idx];
    for (int idx = tid; idx < G2_T * HID; idx += G2_T) {
        size_t gidx = (size_t)row0 * HID + idx;
        float v = (gidx < (size_t)NN * HID) ? g_o1[gidx] : 0.f;
        os[idx / HID][idx % HID] = v;
    }
    __syncthreads();
    int gr = row0 + tid;
    if (gr < NN) {
        float acc[CLS];
        #pragma unroll
        for (int j = 0; j < CLS; j++) acc[j] = 0.f;
        for (int k = 0; k < HID; k++) {
            float v = os[tid][k];
            #pragma unroll
            for (int j = 0; j < CLS; j++) acc[j] += v * w2s[k * CLS + j];
        }
        float d = g_dinv[gr];
        #pragma unroll
        for (int j = 0; j < CLS; j++) g_h2[(size_t)gr * CLS + j] = acc[j] * d;
    }
}

// ---------------- Aggregation layer 2 + bias + log_softmax ----------------------
__global__ void k_agg2(const float* __restrict__ b2, float* __restrict__ out) {
    int warp = (blockIdx.x * blockDim.x + threadIdx.x) >> 5;
    int lane = threadIdx.x & 31;
    if (warp >= NN) return;
    int c = warp;
    int s = g_off[c], e = g_off[c + 1];
    float acc[CLS];
    #pragma unroll
    for (int j = 0; j < CLS; j++) acc[j] = 0.f;
    for (int i = s + lane; i < e; i += 32) {
        int r = g_nbr[i];
        const float* hr = g_h2 + (size_t)r * CLS;
        #pragma unroll
        for (int j = 0; j < CLS; j++) acc[j] += hr[j];
    }
    #pragma unroll
    for (int j = 0; j < CLS; j++) {
        #pragma unroll
        for (int o = 16; o > 0; o >>= 1)
            acc[j] += __shfl_xor_sync(0xffffffffu, acc[j], o);
    }
    if (lane == 0) {
        float d = g_dinv[c];
        const float* hc = g_h2 + (size_t)c * CLS;
        float v[CLS];
        float m = -1e30f;
        #pragma unroll
        for (int j = 0; j < CLS; j++) {
            v[j] = d * (acc[j] + hc[j]) + b2[j];
            m = fmaxf(m, v[j]);
        }
        float sum = 0.f;
        #pragma unroll
        for (int j = 0; j < CLS; j++) sum += __expf(v[j] - m);
        float lse = m + __logf(sum);
        #pragma unroll
        for (int j = 0; j < CLS; j++) out[(size_t)c * CLS + j] = v[j] - lse;
    }
}

// ---------------- launch --------------------------------------------------------
// k_gemm1 stays the 4th launch (ncu capture window). Dependencies preserved.
extern "C" void kernel_launch(void* const* d_in, const int* in_sizes, int n_in,
                              void* d_out, int out_size) {
    const float* x  = (const float*)d_in[0];
    const int*   ei = (const int*)d_in[1];
    const float* W1 = (const float*)d_in[2];
    const float* b1 = (const float*)d_in[3];
    const float* W2 = (const float*)d_in[4];
    const float* b2 = (const float*)d_in[5];
    float* out = (float*)d_out;
    const int* row = ei;        // edge_index[0]
    const int* col = ei + EE;   // edge_index[1]

    k_init<<<(NN + 255) / 256, 256>>>();
    k_count<<<(EE + 255) / 256, 256>>>(col);
    k_dinv<<<(NN + 255) / 256, 256>>>();
    k_gemm1<<<(NN + G1_M - 1) / G1_M, G1_T>>>(x, W1);
    k_scan<<<1, 1024>>>();
    k_scatter<<<(EE + 255) / 256, 256>>>(row, col);
    {
        long long threads = (long long)NN * 32;
        k_agg1<<<(int)((threads + 255) / 256), 256>>>(b1);
    }
    k_gemm2<<<(NN + G2_T - 1) / G2_T, G2_T>>>(W2);
    {
        long long threads = (long long)NN * 32;
        k_agg2<<<(int)((threads + 255) / 256), 256>>>(b2, out);
    }
}

// round 12
// speedup vs baseline: 3.3619x; 1.0907x over previous
#include <cuda_runtime.h>
#include <cstdint>

#define NN 100000
#define EE 3200000
#define FIN 1433
#define HID 67
#define CLS 7

// ---------------- scratch (static device globals; no allocation) ----------------
__device__ int   g_cnt[NN];
__device__ int   g_off[NN + 1];
__device__ int   g_cur[NN];
__device__ int   g_nbr[EE];
__device__ float g_dinv[NN];
__device__ float g_h1[(size_t)NN * HID];   // (x@W1) * dinv[row]
__device__ float g_o1[(size_t)NN * HID];   // leaky_relu(agg1 + b1)
__device__ float g_h2[(size_t)NN * CLS];   // (o1@W2) * dinv[row]

// ---------------- degree counting ----------------
__global__ void k_init() {
    int i = blockIdx.x * blockDim.x + threadIdx.x;
    if (i < NN) g_cnt[i] = 0;
}

__global__ void k_count(const int* __restrict__ col) {
    int e = blockIdx.x * blockDim.x + threadIdx.x;
    if (e < EE) atomicAdd(&g_cnt[col[e]], 1);
}

__global__ void k_dinv() {
    int i = blockIdx.x * blockDim.x + threadIdx.x;
    if (i < NN) g_dinv[i] = rsqrtf((float)(g_cnt[i] + 1));  // +1 self loop
}

// ---------------- exclusive scan of g_cnt -> g_off, g_cur (single block) --------
__global__ void k_scan() {
    __shared__ int wsum[32];
    __shared__ int carry_s;
    int tid = threadIdx.x, lane = tid & 31, wid = tid >> 5;
    if (tid == 0) carry_s = 0;
    __syncthreads();
    for (int base = 0; base < NN; base += 1024) {
        int i = base + tid;
        int v = (i < NN) ? g_cnt[i] : 0;
        int x = v;
        #pragma unroll
        for (int o = 1; o < 32; o <<= 1) {
            int y = __shfl_up_sync(0xffffffffu, x, o);
            if (lane >= o) x += y;
        }
        if (lane == 31) wsum[wid] = x;
        __syncthreads();
        if (wid == 0) {
            int s = wsum[lane];
            #pragma unroll
            for (int o = 1; o < 32; o <<= 1) {
                int y = __shfl_up_sync(0xffffffffu, s, o);
                if (lane >= o) s += y;
            }
            wsum[lane] = s;
        }
        __syncthreads();
        int carry = carry_s;
        int exc = x - v + (wid > 0 ? wsum[wid - 1] : 0);
        if (i < NN) { g_off[i] = carry + exc; g_cur[i] = carry + exc; }
        int tot = wsum[31];
        __syncthreads();
        if (tid == 0) carry_s = carry + tot;
        __syncthreads();
    }
    if (tid == 0) g_off[NN] = carry_s;  // == EE
}

// ---------------- CSR scatter ----------------------------------------------------
__global__ void k_scatter(const int* __restrict__ row, const int* __restrict__ col) {
    int e = blockIdx.x * blockDim.x + threadIdx.x;
    if (e < EE) {
        int c = col[e];
        int p = atomicAdd(&g_cur[c], 1);
        g_nbr[p] = row[e];
    }
}

// ---------------- GEMM1 (warp-MMA tf32, direct-A): h1 = (x @ W1) * dinv[row] ----
// A has no inter-warp reuse -> each warp LDGs its fragments straight from x
// (2 row pointers, 8 LDG.32 with immediate offsets, register double-buffered,
// rows CLAMPED to NN-1 so no predicates; dead rows dropped at the store).
// B (W1^T) staged in smem (shared by 8 warps), ping-pong, k-interleaved,
// stride 26 words (2-way worst-case conflicts). Raw-f32 A bits (tf32 HW reads
// top 19 bits); B cvt.rna. Chunk 89 (k>=1433): clamped A cols x zeroed B rows.
#define G1_T     256
#define G1_M     128
#define G1_KC    16
#define G1_NF    89            // full chunks (k < 1424)
#define G1_NCH   90
#define BSTR     26
#define BBUF     (72 * BSTR)

__device__ __forceinline__ uint32_t tf32(float v) {
    uint32_t u;
    asm("cvt.rna.tf32.f32 %0, %1;" : "=r"(u) : "f"(v));
    return u;
}

__device__ __forceinline__ void mma_tf32(float* d, const uint32_t* a,
                                         uint32_t b0, uint32_t b1) {
    asm volatile(
        "mma.sync.aligned.m16n8k8.row.col.f32.tf32.tf32.f32 "
        "{%0,%1,%2,%3}, {%4,%5,%6,%7}, {%8,%9}, {%0,%1,%2,%3};"
        : "+f"(d[0]), "+f"(d[1]), "+f"(d[2]), "+f"(d[3])
        : "r"(a[0]), "r"(a[1]), "r"(a[2]), "r"(a[3]), "r"(b0), "r"(b1));
}

__global__ __launch_bounds__(G1_T, 3) void k_gemm1(const float* __restrict__ x,
                                                   const float* __restrict__ W1) {
    __shared__ __align__(16) float Bs[2][BBUF];
    const int il[8] = {0, 2, 4, 6, 1, 3, 5, 7};
    int tid = threadIdx.x;
    int lane = tid & 31, w = tid >> 5;
    int g = lane >> 2, t = lane & 3;
    int row0 = blockIdx.x * G1_M + w * 16;

    int rg0 = min(row0 + g, NN - 1);
    int rg8 = min(row0 + 8 + g, NN - 1);
    const float* pA0 = x + (size_t)rg0 * FIN + t;
    const float* pA1 = x + (size_t)rg8 * FIN + t;

    bool bstage = tid < 144;
    int bn = tid % 72;
    int bk0 = (tid / 72) * 8;
    bool bnok = bn < HID;
    const float* pB = W1 + bk0 * HID + bn;
    int bsts = bn * BSTR + bk0;   // word offset in Bs buffer

    float acc[9][4];
    #pragma unroll
    for (int nt = 0; nt < 9; nt++)
        #pragma unroll
        for (int q = 0; q < 4; q++) acc[nt][q] = 0.f;

    float pc[8], pn[8], pw[8];

    // ---- chunk 0: load A regs + stage B buffer 0 ----
    #pragma unroll
    for (int j = 0; j < 4; j++) { pc[j] = pA0[4 * j]; pc[4 + j] = pA1[4 * j]; }
    pA0 += G1_KC; pA1 += G1_KC;
    if (bstage) {
        #pragma unroll
        for (int j = 0; j < 8; j++) pw[j] = bnok ? pB[j * HID] : 0.f;
        #pragma unroll
        for (int j = 0; j < 8; j++)
            Bs[0][bsts + il[j]] = __uint_as_float(tf32(pw[j]));
    }
    pB += G1_KC * HID;
    __syncthreads();

    for (int c = 0; c < G1_NCH; c++) {
        int buf = c & 1;

        // prefetch chunk c+1
        if (c + 1 < G1_NCH) {
            if (c + 1 < G1_NF) {        // fully in-bounds, zero predicates
                #pragma unroll
                for (int j = 0; j < 4; j++) { pn[j] = pA0[4 * j]; pn[4 + j] = pA1[4 * j]; }
                if (bstage) {
                    #pragma unroll
                    for (int j = 0; j < 8; j++) pw[j] = bnok ? pB[j * HID] : 0.f;
                }
            } else {                     // chunk 89: clamp A cols, zero B OOB rows
                #pragma unroll
                for (int j = 0; j < 4; j++) {
                    int off = min(4 * j, 8 - t);   // keeps col <= 1432
                    pn[j] = pA0[off]; pn[4 + j] = pA1[off];
                }
                if (bstage) {
                    #pragma unroll
                    for (int j = 0; j < 8; j++) {
                        int k = G1_NF * G1_KC + bk0 + j;
                        pw[j] = (bnok && k < FIN) ? pB[j * HID] : 0.f;
                    }
                }
            }
            pA0 += G1_KC; pA1 += G1_KC; pB += G1_KC * HID;
        }

        // compute chunk c: A from regs, B from Bs[buf]
        #pragma unroll
        for (int s = 0; s < 2; s++) {
            uint32_t af[4];
            af[0] = __float_as_uint(pc[2 * s + 0]);
            af[1] = __float_as_uint(pc[2 * s + 4]);
            af[2] = __float_as_uint(pc[2 * s + 1]);
            af[3] = __float_as_uint(pc[2 * s + 5]);
            const float* bb = &Bs[buf][g * BSTR + s * 8 + 2 * t];
            #pragma unroll
            for (int nt = 0; nt < 9; nt++) {
                float blo = bb[nt * 8 * BSTR];
                float bhi = bb[nt * 8 * BSTR + 1];
                mma_tf32(acc[nt], af, __float_as_uint(blo), __float_as_uint(bhi));
            }
        }

        if (c + 1 < G1_NCH) {
            if (bstage) {
                #pragma unroll
                for (int j = 0; j < 8; j++)
                    Bs[buf ^ 1][bsts + il[j]] = __uint_as_float(tf32(pw[j]));
            }
            __syncthreads();
            #pragma unroll
            for (int j = 0; j < 8; j++) pc[j] = pn[j];
        }
    }

    // epilogue: c0(row g,col 2t) c1(row g,2t+1) c2(row g+8,2t) c3(row g+8,2t+1)
    int r0 = row0 + g;
    int r1 = r0 + 8;
    float d0 = (r0 < NN) ? g_dinv[r0] : 0.f;
    float d1 = (r1 < NN) ? g_dinv[r1] : 0.f;
    #pragma unroll
    for (int nt = 0; nt < 9; nt++) {
        int col = nt * 8 + 2 * t;
        if (col < HID) {
            if (r0 < NN) g_h1[(size_t)r0 * HID + col] = acc[nt][0] * d0;
            if (r1 < NN) g_h1[(size_t)r1 * HID + col] = acc[nt][2] * d1;
        }
        if (col + 1 < HID) {
            if (r0 < NN) g_h1[(size_t)r0 * HID + col + 1] = acc[nt][1] * d0;
            if (r1 < NN) g_h1[(size_t)r1 * HID + col + 1] = acc[nt][3] * d1;
        }
    }
}

// ---------------- Aggregation layer 1 (warp per node, lane per feature) ---------
__global__ void k_agg1(const float* __restrict__ b1) {
    int warp = (blockIdx.x * blockDim.x + threadIdx.x) >> 5;
    int lane = threadIdx.x & 31;
    if (warp >= NN) return;
    int c = warp;
    int s = g_off[c], e = g_off[c + 1];
    bool p1 = lane < (HID - 32);
    bool p2 = lane < (HID - 64);
    float a0 = 0.f, a1 = 0.f, a2 = 0.f;
    for (int i = s; i < e; i++) {
        int r = g_nbr[i];  // broadcast load
        const float* hr = g_h1 + (size_t)r * HID;
        a0 += hr[lane];
        if (p1) a1 += hr[lane + 32];
        if (p2) a2 += hr[lane + 64];
    }
    const float* hc = g_h1 + (size_t)c * HID;  // self loop (pre-scaled by dinv[c])
    a0 += hc[lane];
    if (p1) a1 += hc[lane + 32];
    if (p2) a2 += hc[lane + 64];

    float d = g_dinv[c];
    float* oc = g_o1 + (size_t)c * HID;
    {
        float v = d * a0 + b1[lane];
        oc[lane] = v > 0.f ? v : 0.01f * v;
    }
    if (p1) {
        float v = d * a1 + b1[lane + 32];
        oc[lane + 32] = v > 0.f ? v : 0.01f * v;
    }
    if (p2) {
        float v = d * a2 + b1[lane + 64];
        oc[lane + 64] = v > 0.f ? v : 0.01f * v;
    }
}

// ---------------- GEMM2: h2 = (o1 @ W2) * dinv[row] -----------------------------
#define G2_T 128
__global__ void k_gemm2(const float* __restrict__ W2) {
    __shared__ float w2s[HID * CLS];
    __shared__ float os[G2_T][HID + 2];
    int tid = threadIdx.x;
    int row0 = blockIdx.x * G2_T;
    for (int idx = tid; idx < HID * CLS; idx += G2_T) w2s[idx] = W2[idx];
    for (int idx = tid; idx < G2_T * HID; idx += G2_T) {
        size_t gidx = (size_t)row0 * HID + idx;
        float v = (gidx < (size_t)NN * HID) ? g_o1[gidx] : 0.f;
        os[idx / HID][idx % HID] = v;
    }
    __syncthreads();
    int gr = row0 + tid;
    if (gr < NN) {
        float acc[CLS];
        #pragma unroll
        for (int j = 0; j < CLS; j++) acc[j] = 0.f;
        for (int k = 0; k < HID; k++) {
            float v = os[tid][k];
            #pragma unroll
            for (int j = 0; j < CLS; j++) acc[j] += v * w2s[k * CLS + j];
        }
        float d = g_dinv[gr];
        #pragma unroll
        for (int j = 0; j < CLS; j++) g_h2[(size_t)gr * CLS + j] = acc[j] * d;
    }
}

// ---------------- Aggregation layer 2 + bias + log_softmax ----------------------
__global__ void k_agg2(const float* __restrict__ b2, float* __restrict__ out) {
    int warp = (blockIdx.x * blockDim.x + threadIdx.x) >> 5;
    int lane = threadIdx.x & 31;
    if (warp >= NN) return;
    int c = warp;
    int s = g_off[c], e = g_off[c + 1];
    float acc[CLS];
    #pragma unroll
    for (int j = 0; j < CLS; j++) acc[j] = 0.f;
    for (int i = s + lane; i < e; i += 32) {
        int r = g_nbr[i];
        const float* hr = g_h2 + (size_t)r * CLS;
        #pragma unroll
        for (int j = 0; j < CLS; j++) acc[j] += hr[j];
    }
    #pragma unroll
    for (int j = 0; j < CLS; j++) {
        #pragma unroll
        for (int o = 16; o > 0; o >>= 1)
            acc[j] += __shfl_xor_sync(0xffffffffu, acc[j], o);
    }
    if (lane == 0) {
        float d = g_dinv[c];
        const float* hc = g_h2 + (size_t)c * CLS;
        float v[CLS];
        float m = -1e30f;
        #pragma unroll
        for (int j = 0; j < CLS; j++) {
            v[j] = d * (acc[j] + hc[j]) + b2[j];
            m = fmaxf(m, v[j]);
        }
        float sum = 0.f;
        #pragma unroll
        for (int j = 0; j < CLS; j++) sum += __expf(v[j] - m);
        float lse = m + __logf(sum);
        #pragma unroll
        for (int j = 0; j < CLS; j++) out[(size_t)c * CLS + j] = v[j] - lse;
    }
}

// ---------------- launch --------------------------------------------------------
// k_gemm1 stays the 4th launch (ncu capture window). Dependencies preserved.
extern "C" void kernel_launch(void* const* d_in, const int* in_sizes, int n_in,
                              void* d_out, int out_size) {
    const float* x  = (const float*)d_in[0];
    const int*   ei = (const int*)d_in[1];
    const float* W1 = (const float*)d_in[2];
    const float* b1 = (const float*)d_in[3];
    const float* W2 = (const float*)d_in[4];
    const float* b2 = (const float*)d_in[5];
    float* out = (float*)d_out;
    const int* row = ei;        // edge_index[0]
    const int* col = ei + EE;   // edge_index[1]

    k_init<<<(NN + 255) / 256, 256>>>();
    k_count<<<(EE + 255) / 256, 256>>>(col);
    k_dinv<<<(NN + 255) / 256, 256>>>();
    k_gemm1<<<(NN + G1_M - 1) / G1_M, G1_T>>>(x, W1);
    k_scan<<<1, 1024>>>();
    k_scatter<<<(EE + 255) / 256, 256>>>(row, col);
    {
        long long threads = (long long)NN * 32;
        k_agg1<<<(int)((threads + 255) / 256), 256>>>(b1);
    }
    k_gemm2<<<(NN + G2_T - 1) / G2_T, G2_T>>>(W2);
    {
        long long threads = (long long)NN * 32;
        k_agg2<<<(int)((threads + 255) / 256), 256>>>(b2, out);
    }
}

// round 13
// speedup vs baseline: 3.4474x; 1.0254x over previous
#include <cuda_runtime.h>
#include <cstdint>

#define NN 100000
#define EE 3200000
#define FIN 1433
#define HID 67
#define H1P 68          // padded h1/o1 row stride (16B-aligned, col 67 == 0)
#define CLS 7
#define H2P 8           // padded h2 row stride (32B-aligned, col 7 == 0)

// ---------------- scratch (static device globals; zero-initialized) -------------
__device__ int   g_cnt[NN];
__device__ int   g_off[NN + 1];
__device__ int   g_cur[NN];
__device__ int   g_nbr[EE];
__device__ float g_dinv[NN];
__device__ float g_h1[(size_t)NN * H1P];   // (x@W1) * dinv[row], padded
__device__ float g_o1[(size_t)NN * H1P];   // leaky_relu(agg1 + b1), padded
__device__ float g_h2[(size_t)NN * H2P];   // (o1@W2) * dinv[row], padded

// ---------------- degree counting ----------------
__global__ void k_init() {
    int i = blockIdx.x * blockDim.x + threadIdx.x;
    if (i < NN) g_cnt[i] = 0;
}

__global__ void k_count(const int* __restrict__ col) {
    int e = blockIdx.x * blockDim.x + threadIdx.x;
    if (e < EE) atomicAdd(&g_cnt[col[e]], 1);
}

__global__ void k_dinv() {
    int i = blockIdx.x * blockDim.x + threadIdx.x;
    if (i < NN) g_dinv[i] = rsqrtf((float)(g_cnt[i] + 1));  // +1 self loop
}

// ---------------- exclusive scan of g_cnt -> g_off, g_cur (single block) --------
__global__ void k_scan() {
    __shared__ int wsum[32];
    __shared__ int carry_s;
    int tid = threadIdx.x, lane = tid & 31, wid = tid >> 5;
    if (tid == 0) carry_s = 0;
    __syncthreads();
    for (int base = 0; base < NN; base += 1024) {
        int i = base + tid;
        int v = (i < NN) ? g_cnt[i] : 0;
        int x = v;
        #pragma unroll
        for (int o = 1; o < 32; o <<= 1) {
            int y = __shfl_up_sync(0xffffffffu, x, o);
            if (lane >= o) x += y;
        }
        if (lane == 31) wsum[wid] = x;
        __syncthreads();
        if (wid == 0) {
            int s = wsum[lane];
            #pragma unroll
            for (int o = 1; o < 32; o <<= 1) {
                int y = __shfl_up_sync(0xffffffffu, s, o);
                if (lane >= o) s += y;
            }
            wsum[lane] = s;
        }
        __syncthreads();
        int carry = carry_s;
        int exc = x - v + (wid > 0 ? wsum[wid - 1] : 0);
        if (i < NN) { g_off[i] = carry + exc; g_cur[i] = carry + exc; }
        int tot = wsum[31];
        __syncthreads();
        if (tid == 0) carry_s = carry + tot;
        __syncthreads();
    }
    if (tid == 0) g_off[NN] = carry_s;  // == EE
}

// ---------------- CSR scatter ----------------------------------------------------
__global__ void k_scatter(const int* __restrict__ row, const int* __restrict__ col) {
    int e = blockIdx.x * blockDim.x + threadIdx.x;
    if (e < EE) {
        int c = col[e];
        int p = atomicAdd(&g_cur[c], 1);
        g_nbr[p] = row[e];
    }
}

// ---------------- GEMM1 (warp-MMA tf32, direct-A): h1 = (x @ W1) * dinv[row] ----
#define G1_T     256
#define G1_M     128
#define G1_KC    16
#define G1_NF    89            // full chunks (k < 1424)
#define G1_NCH   90
#define BSTR     26
#define BBUF     (72 * BSTR)

__device__ __forceinline__ uint32_t tf32(float v) {
    uint32_t u;
    asm("cvt.rna.tf32.f32 %0, %1;" : "=r"(u) : "f"(v));
    return u;
}

__device__ __forceinline__ void mma_tf32(float* d, const uint32_t* a,
                                         uint32_t b0, uint32_t b1) {
    asm volatile(
        "mma.sync.aligned.m16n8k8.row.col.f32.tf32.tf32.f32 "
        "{%0,%1,%2,%3}, {%4,%5,%6,%7}, {%8,%9}, {%0,%1,%2,%3};"
        : "+f"(d[0]), "+f"(d[1]), "+f"(d[2]), "+f"(d[3])
        : "r"(a[0]), "r"(a[1]), "r"(a[2]), "r"(a[3]), "r"(b0), "r"(b1));
}

__global__ __launch_bounds__(G1_T, 3) void k_gemm1(const float* __restrict__ x,
                                                   const float* __restrict__ W1) {
    __shared__ __align__(16) float Bs[2][BBUF];
    const int il[8] = {0, 2, 4, 6, 1, 3, 5, 7};
    int tid = threadIdx.x;
    int lane = tid & 31, w = tid >> 5;
    int g = lane >> 2, t = lane & 3;
    int row0 = blockIdx.x * G1_M + w * 16;

    int rg0 = min(row0 + g, NN - 1);
    int rg8 = min(row0 + 8 + g, NN - 1);
    const float* pA0 = x + (size_t)rg0 * FIN + t;
    const float* pA1 = x + (size_t)rg8 * FIN + t;

    bool bstage = tid < 144;
    int bn = tid % 72;
    int bk0 = (tid / 72) * 8;
    bool bnok = bn < HID;
    const float* pB = W1 + bk0 * HID + bn;
    int bsts = bn * BSTR + bk0;   // word offset in Bs buffer

    float acc[9][4];
    #pragma unroll
    for (int nt = 0; nt < 9; nt++)
        #pragma unroll
        for (int q = 0; q < 4; q++) acc[nt][q] = 0.f;

    float pc[8], pn[8], pw[8];

    // ---- chunk 0: load A regs + stage B buffer 0 ----
    #pragma unroll
    for (int j = 0; j < 4; j++) { pc[j] = pA0[4 * j]; pc[4 + j] = pA1[4 * j]; }
    pA0 += G1_KC; pA1 += G1_KC;
    if (bstage) {
        #pragma unroll
        for (int j = 0; j < 8; j++) pw[j] = bnok ? pB[j * HID] : 0.f;
        #pragma unroll
        for (int j = 0; j < 8; j++)
            Bs[0][bsts + il[j]] = __uint_as_float(tf32(pw[j]));
    }
    pB += G1_KC * HID;
    __syncthreads();

    for (int c = 0; c < G1_NCH; c++) {
        int buf = c & 1;

        // prefetch chunk c+1
        if (c + 1 < G1_NCH) {
            if (c + 1 < G1_NF) {        // fully in-bounds, zero predicates
                #pragma unroll
                for (int j = 0; j < 4; j++) { pn[j] = pA0[4 * j]; pn[4 + j] = pA1[4 * j]; }
                if (bstage) {
                    #pragma unroll
                    for (int j = 0; j < 8; j++) pw[j] = bnok ? pB[j * HID] : 0.f;
                }
            } else {                     // chunk 89: clamp A cols, zero B OOB rows
                #pragma unroll
                for (int j = 0; j < 4; j++) {
                    int off = min(4 * j, 8 - t);   // keeps col <= 1432
                    pn[j] = pA0[off]; pn[4 + j] = pA1[off];
                }
                if (bstage) {
                    #pragma unroll
                    for (int j = 0; j < 8; j++) {
                        int k = G1_NF * G1_KC + bk0 + j;
                        pw[j] = (bnok && k < FIN) ? pB[j * HID] : 0.f;
                    }
                }
            }
            pA0 += G1_KC; pA1 += G1_KC; pB += G1_KC * HID;
        }

        // compute chunk c: A from regs, B from Bs[buf]
        #pragma unroll
        for (int s = 0; s < 2; s++) {
            uint32_t af[4];
            af[0] = __float_as_uint(pc[2 * s + 0]);
            af[1] = __float_as_uint(pc[2 * s + 4]);
            af[2] = __float_as_uint(pc[2 * s + 1]);
            af[3] = __float_as_uint(pc[2 * s + 5]);
            const float* bb = &Bs[buf][g * BSTR + s * 8 + 2 * t];
            #pragma unroll
            for (int nt = 0; nt < 9; nt++) {
                float blo = bb[nt * 8 * BSTR];
                float bhi = bb[nt * 8 * BSTR + 1];
                mma_tf32(acc[nt], af, __float_as_uint(blo), __float_as_uint(bhi));
            }
        }

        if (c + 1 < G1_NCH) {
            if (bstage) {
                #pragma unroll
                for (int j = 0; j < 8; j++)
                    Bs[buf ^ 1][bsts + il[j]] = __uint_as_float(tf32(pw[j]));
            }
            __syncthreads();
            #pragma unroll
            for (int j = 0; j < 8; j++) pc[j] = pn[j];
        }
    }

    // epilogue (padded stride H1P; col 67 never written -> stays 0)
    int r0 = row0 + g;
    int r1 = r0 + 8;
    float d0 = (r0 < NN) ? g_dinv[r0] : 0.f;
    float d1 = (r1 < NN) ? g_dinv[r1] : 0.f;
    #pragma unroll
    for (int nt = 0; nt < 9; nt++) {
        int col = nt * 8 + 2 * t;
        if (col < HID) {
            if (r0 < NN) g_h1[(size_t)r0 * H1P + col] = acc[nt][0] * d0;
            if (r1 < NN) g_h1[(size_t)r1 * H1P + col] = acc[nt][2] * d1;
        }
        if (col + 1 < HID) {
            if (r0 < NN) g_h1[(size_t)r0 * H1P + col + 1] = acc[nt][1] * d0;
            if (r1 < NN) g_h1[(size_t)r1 * H1P + col + 1] = acc[nt][3] * d1;
        }
    }
}

// ---------------- Aggregation layer 1 (warp/node; lanes 0..16 x float4) ---------
__global__ void k_agg1(const float* __restrict__ b1) {
    int warp = (blockIdx.x * blockDim.x + threadIdx.x) >> 5;
    int lane = threadIdx.x & 31;
    if (warp >= NN || lane >= 17) return;
    int c = warp;
    int s = g_off[c], e = g_off[c + 1];

    float4 a = make_float4(0.f, 0.f, 0.f, 0.f);
    const float4* h14 = reinterpret_cast<const float4*>(g_h1);
    for (int i = s; i < e; i++) {
        int r = g_nbr[i];                       // uniform across active lanes
        float4 v = h14[(size_t)r * 17 + lane];  // one LDG.128 per lane
        a.x += v.x; a.y += v.y; a.z += v.z; a.w += v.w;
    }
    {   // self loop (h1 pre-scaled by dinv[c])
        float4 v = h14[(size_t)c * 17 + lane];
        a.x += v.x; a.y += v.y; a.z += v.z; a.w += v.w;
    }

    int cb = lane * 4;
    float4 bv;
    bv.x = b1[cb];
    bv.y = (cb + 1 < HID) ? b1[cb + 1] : 0.f;
    bv.z = (cb + 2 < HID) ? b1[cb + 2] : 0.f;
    bv.w = (cb + 3 < HID) ? b1[cb + 3] : 0.f;

    float d = g_dinv[c];
    float4 o;
    o.x = d * a.x + bv.x;  o.x = o.x > 0.f ? o.x : 0.01f * o.x;
    o.y = d * a.y + bv.y;  o.y = o.y > 0.f ? o.y : 0.01f * o.y;
    o.z = d * a.z + bv.z;  o.z = o.z > 0.f ? o.z : 0.01f * o.z;
    o.w = d * a.w + bv.w;  o.w = o.w > 0.f ? o.w : 0.01f * o.w;
    if (lane == 16) o.w = 0.f;   // keep pad column zero
    reinterpret_cast<float4*>(g_o1)[(size_t)c * 17 + lane] = o;
}

// ---------------- GEMM2: h2 = (o1 @ W2) * dinv[row] (padded in/out) -------------
#define G2_T 128
__global__ void k_gemm2(const float* __restrict__ W2) {
    __shared__ float w2s[HID * CLS];
    __shared__ float os[G2_T][HID + 2];
    int tid = threadIdx.x;
    int row0 = blockIdx.x * G2_T;
    for (int idx = tid; idx < HID * CLS; idx += G2_T) w2s[idx] = W2[idx];
    for (int idx = tid; idx < G2_T * HID; idx += G2_T) {
        int r = idx / HID, k = idx % HID;
        int gr = row0 + r;
        os[r][k] = (gr < NN) ? g_o1[(size_t)gr * H1P + k] : 0.f;
    }
    __syncthreads();
    int gr = row0 + tid;
    if (gr < NN) {
        float acc[CLS];
        #pragma unroll
        for (int j = 0; j < CLS; j++) acc[j] = 0.f;
        for (int k = 0; k < HID; k++) {
            float v = os[tid][k];
            #pragma unroll
            for (int j = 0; j < CLS; j++) acc[j] += v * w2s[k * CLS + j];
        }
        float d = g_dinv[gr];
        #pragma unroll
        for (int j = 0; j < CLS; j++) g_h2[(size_t)gr * H2P + j] = acc[j] * d;
        // col 7 stays 0 (zero-init, never written)
    }
}

// ---------------- Aggregation layer 2 + bias + log_softmax ----------------------
__global__ void k_agg2(const float* __restrict__ b2, float* __restrict__ out) {
    int warp = (blockIdx.x * blockDim.x + threadIdx.x) >> 5;
    int lane = threadIdx.x & 31;
    if (warp >= NN) return;
    int c = warp;
    int s = g_off[c], e = g_off[c + 1];
    float acc[8];
    #pragma unroll
    for (int j = 0; j < 8; j++) acc[j] = 0.f;
    const float4* h24 = reinterpret_cast<const float4*>(g_h2);
    for (int i = s + lane; i < e; i += 32) {
        int r = g_nbr[i];
        float4 lo = h24[(size_t)r * 2];       // 2x LDG.128 per edge-lane
        float4 hi = h24[(size_t)r * 2 + 1];
        acc[0] += lo.x; acc[1] += lo.y; acc[2] += lo.z; acc[3] += lo.w;
        acc[4] += hi.x; acc[5] += hi.y; acc[6] += hi.z; acc[7] += hi.w;
    }
    #pragma unroll
    for (int j = 0; j < CLS; j++) {
        #pragma unroll
        for (int o = 16; o > 0; o >>= 1)
            acc[j] += __shfl_xor_sync(0xffffffffu, acc[j], o);
    }
    if (lane == 0) {
        float d = g_dinv[c];
        const float* hc = g_h2 + (size_t)c * H2P;
        float v[CLS];
        float m = -1e30f;
        #pragma unroll
        for (int j = 0; j < CLS; j++) {
            v[j] = d * (acc[j] + hc[j]) + b2[j];
            m = fmaxf(m, v[j]);
        }
        float sum = 0.f;
        #pragma unroll
        for (int j = 0; j < CLS; j++) sum += __expf(v[j] - m);
        float lse = m + __logf(sum);
        #pragma unroll
        for (int j = 0; j < CLS; j++) out[(size_t)c * CLS + j] = v[j] - lse;
    }
}

// ---------------- launch --------------------------------------------------------
// k_gemm1 stays the 4th launch (ncu capture window). Dependencies preserved.
extern "C" void kernel_launch(void* const* d_in, const int* in_sizes, int n_in,
                              void* d_out, int out_size) {
    const float* x  = (const float*)d_in[0];
    const int*   ei = (const int*)d_in[1];
    const float* W1 = (const float*)d_in[2];
    const float* b1 = (const float*)d_in[3];
    const float* W2 = (const float*)d_in[4];
    const float* b2 = (const float*)d_in[5];
    float* out = (float*)d_out;
    const int* row = ei;        // edge_index[0]
    const int* col = ei + EE;   // edge_index[1]

    k_init<<<(NN + 255) / 256, 256>>>();
    k_count<<<(EE + 255) / 256, 256>>>(col);
    k_dinv<<<(NN + 255) / 256, 256>>>();
    k_gemm1<<<(NN + G1_M - 1) / G1_M, G1_T>>>(x, W1);
    k_scan<<<1, 1024>>>();
    k_scatter<<<(EE + 255) / 256, 256>>>(row, col);
    {
        long long threads = (long long)NN * 32;
        k_agg1<<<(int)((threads + 255) / 256), 256>>>(b1);
    }
    k_gemm2<<<(NN + G2_T - 1) / G2_T, G2_T>>>(W2);
    {
        long long threads = (long long)NN * 32;
        k_agg2<<<(int)((threads + 255) / 256), 256>>>(b2, out);
    }
}

// round 14
// speedup vs baseline: 4.2207x; 1.2243x over previous
#include <cuda_runtime.h>
#include <cstdint>

#define NN 100000
#define EE 3200000
#define FIN 1433
#define HID 67
#define H1P 68          // padded h1/o1 row stride (16B-aligned, col 67 == 0)
#define CLS 7
#define H2P 8           // padded h2 row stride (32B-aligned, col 7 == 0)

// ---------------- scratch (static device globals; zero-initialized) -------------
__device__ int   g_cnt[NN];
__device__ int   g_off[NN + 1];
__device__ int   g_cur[NN];
__device__ int   g_nbr[EE];
__device__ float g_dinv[NN];
__device__ float g_h1[(size_t)NN * H1P];   // x@W1 (UNscaled), padded
__device__ float g_o1[(size_t)NN * H1P];   // leaky_relu(agg1 + b1), padded
__device__ float g_h2[(size_t)NN * H2P];   // (o1@W2) * dinv[row], padded

// ---------------- degree counting ----------------
__global__ void k_init() {
    int i = blockIdx.x * blockDim.x + threadIdx.x;
    if (i < NN) g_cnt[i] = 0;
}

__global__ void k_count(const int* __restrict__ col) {
    int e = blockIdx.x * blockDim.x + threadIdx.x;
    if (e < EE) atomicAdd(&g_cnt[col[e]], 1);
}

__global__ void k_dinv() {
    int i = blockIdx.x * blockDim.x + threadIdx.x;
    if (i < NN) g_dinv[i] = rsqrtf((float)(g_cnt[i] + 1));  // +1 self loop
}

// ---------------- exclusive scan of g_cnt -> g_off, g_cur (single block) --------
__global__ void k_scan() {
    __shared__ int wsum[32];
    __shared__ int carry_s;
    int tid = threadIdx.x, lane = tid & 31, wid = tid >> 5;
    if (tid == 0) carry_s = 0;
    __syncthreads();
    for (int base = 0; base < NN; base += 1024) {
        int i = base + tid;
        int v = (i < NN) ? g_cnt[i] : 0;
        int x = v;
        #pragma unroll
        for (int o = 1; o < 32; o <<= 1) {
            int y = __shfl_up_sync(0xffffffffu, x, o);
            if (lane >= o) x += y;
        }
        if (lane == 31) wsum[wid] = x;
        __syncthreads();
        if (wid == 0) {
            int s = wsum[lane];
            #pragma unroll
            for (int o = 1; o < 32; o <<= 1) {
                int y = __shfl_up_sync(0xffffffffu, s, o);
                if (lane >= o) s += y;
            }
            wsum[lane] = s;
        }
        __syncthreads();
        int carry = carry_s;
        int exc = x - v + (wid > 0 ? wsum[wid - 1] : 0);
        if (i < NN) { g_off[i] = carry + exc; g_cur[i] = carry + exc; }
        int tot = wsum[31];
        __syncthreads();
        if (tid == 0) carry_s = carry + tot;
        __syncthreads();
    }
    if (tid == 0) g_off[NN] = carry_s;  // == EE
}

// ---------------- CSR scatter ----------------------------------------------------
__global__ void k_scatter(const int* __restrict__ row, const int* __restrict__ col) {
    int e = blockIdx.x * blockDim.x + threadIdx.x;
    if (e < EE) {
        int c = col[e];
        int p = atomicAdd(&g_cur[c], 1);
        g_nbr[p] = row[e];
    }
}

// ---------------- GEMM1 (warp-MMA tf32, direct-A): h1 = x @ W1 (unscaled) -------
// Depends ONLY on x, W1 -> runs on a forked stream concurrently with the
// edge-processing chain. dinv folded into agg1.
#define G1_T     256
#define G1_M     128
#define G1_KC    16
#define G1_NF    89            // full chunks (k < 1424)
#define G1_NCH   90
#define BSTR     26
#define BBUF     (72 * BSTR)

__device__ __forceinline__ uint32_t tf32(float v) {
    uint32_t u;
    asm("cvt.rna.tf32.f32 %0, %1;" : "=r"(u) : "f"(v));
    return u;
}

__device__ __forceinline__ void mma_tf32(float* d, const uint32_t* a,
                                         uint32_t b0, uint32_t b1) {
    asm volatile(
        "mma.sync.aligned.m16n8k8.row.col.f32.tf32.tf32.f32 "
        "{%0,%1,%2,%3}, {%4,%5,%6,%7}, {%8,%9}, {%0,%1,%2,%3};"
        : "+f"(d[0]), "+f"(d[1]), "+f"(d[2]), "+f"(d[3])
        : "r"(a[0]), "r"(a[1]), "r"(a[2]), "r"(a[3]), "r"(b0), "r"(b1));
}

__global__ __launch_bounds__(G1_T, 3) void k_gemm1(const float* __restrict__ x,
                                                   const float* __restrict__ W1) {
    __shared__ __align__(16) float Bs[2][BBUF];
    const int il[8] = {0, 2, 4, 6, 1, 3, 5, 7};
    int tid = threadIdx.x;
    int lane = tid & 31, w = tid >> 5;
    int g = lane >> 2, t = lane & 3;
    int row0 = blockIdx.x * G1_M + w * 16;

    int rg0 = min(row0 + g, NN - 1);
    int rg8 = min(row0 + 8 + g, NN - 1);
    const float* pA0 = x + (size_t)rg0 * FIN + t;
    const float* pA1 = x + (size_t)rg8 * FIN + t;

    bool bstage = tid < 144;
    int bn = tid % 72;
    int bk0 = (tid / 72) * 8;
    bool bnok = bn < HID;
    const float* pB = W1 + bk0 * HID + bn;
    int bsts = bn * BSTR + bk0;   // word offset in Bs buffer

    float acc[9][4];
    #pragma unroll
    for (int nt = 0; nt < 9; nt++)
        #pragma unroll
        for (int q = 0; q < 4; q++) acc[nt][q] = 0.f;

    float pc[8], pn[8], pw[8];

    // ---- chunk 0: load A regs + stage B buffer 0 ----
    #pragma unroll
    for (int j = 0; j < 4; j++) { pc[j] = pA0[4 * j]; pc[4 + j] = pA1[4 * j]; }
    pA0 += G1_KC; pA1 += G1_KC;
    if (bstage) {
        #pragma unroll
        for (int j = 0; j < 8; j++) pw[j] = bnok ? pB[j * HID] : 0.f;
        #pragma unroll
        for (int j = 0; j < 8; j++)
            Bs[0][bsts + il[j]] = __uint_as_float(tf32(pw[j]));
    }
    pB += G1_KC * HID;
    __syncthreads();

    for (int c = 0; c < G1_NCH; c++) {
        int buf = c & 1;

        // prefetch chunk c+1
        if (c + 1 < G1_NCH) {
            if (c + 1 < G1_NF) {        // fully in-bounds, zero predicates
                #pragma unroll
                for (int j = 0; j < 4; j++) { pn[j] = pA0[4 * j]; pn[4 + j] = pA1[4 * j]; }
                if (bstage) {
                    #pragma unroll
                    for (int j = 0; j < 8; j++) pw[j] = bnok ? pB[j * HID] : 0.f;
                }
            } else {                     // chunk 89: clamp A cols, zero B OOB rows
                #pragma unroll
                for (int j = 0; j < 4; j++) {
                    int off = min(4 * j, 8 - t);   // keeps col <= 1432
                    pn[j] = pA0[off]; pn[4 + j] = pA1[off];
                }
                if (bstage) {
                    #pragma unroll
                    for (int j = 0; j < 8; j++) {
                        int k = G1_NF * G1_KC + bk0 + j;
                        pw[j] = (bnok && k < FIN) ? pB[j * HID] : 0.f;
                    }
                }
            }
            pA0 += G1_KC; pA1 += G1_KC; pB += G1_KC * HID;
        }

        // compute chunk c: A from regs, B from Bs[buf]
        #pragma unroll
        for (int s = 0; s < 2; s++) {
            uint32_t af[4];
            af[0] = __float_as_uint(pc[2 * s + 0]);
            af[1] = __float_as_uint(pc[2 * s + 4]);
            af[2] = __float_as_uint(pc[2 * s + 1]);
            af[3] = __float_as_uint(pc[2 * s + 5]);
            const float* bb = &Bs[buf][g * BSTR + s * 8 + 2 * t];
            #pragma unroll
            for (int nt = 0; nt < 9; nt++) {
                float blo = bb[nt * 8 * BSTR];
                float bhi = bb[nt * 8 * BSTR + 1];
                mma_tf32(acc[nt], af, __float_as_uint(blo), __float_as_uint(bhi));
            }
        }

        if (c + 1 < G1_NCH) {
            if (bstage) {
                #pragma unroll
                for (int j = 0; j < 8; j++)
                    Bs[buf ^ 1][bsts + il[j]] = __uint_as_float(tf32(pw[j]));
            }
            __syncthreads();
            #pragma unroll
            for (int j = 0; j < 8; j++) pc[j] = pn[j];
        }
    }

    // epilogue: store RAW acc (padded stride H1P; col 67 never written -> 0)
    int r0 = row0 + g;
    int r1 = r0 + 8;
    #pragma unroll
    for (int nt = 0; nt < 9; nt++) {
        int col = nt * 8 + 2 * t;
        if (col < HID) {
            if (r0 < NN) g_h1[(size_t)r0 * H1P + col] = acc[nt][0];
            if (r1 < NN) g_h1[(size_t)r1 * H1P + col] = acc[nt][2];
        }
        if (col + 1 < HID) {
            if (r0 < NN) g_h1[(size_t)r0 * H1P + col + 1] = acc[nt][1];
            if (r1 < NN) g_h1[(size_t)r1 * H1P + col + 1] = acc[nt][3];
        }
    }
}

// ---------------- Aggregation layer 1 (warp/node; lanes 0..16 x float4) ---------
// h1 is UNscaled; scale each neighbor by dinv[r] here (fma), self by dinv[c].
__global__ void k_agg1(const float* __restrict__ b1) {
    int warp = (blockIdx.x * blockDim.x + threadIdx.x) >> 5;
    int lane = threadIdx.x & 31;
    if (warp >= NN || lane >= 17) return;
    int c = warp;
    int s = g_off[c], e = g_off[c + 1];

    float4 a = make_float4(0.f, 0.f, 0.f, 0.f);
    const float4* h14 = reinterpret_cast<const float4*>(g_h1);
    for (int i = s; i < e; i++) {
        int r = g_nbr[i];                       // uniform across active lanes
        float dr = g_dinv[r];
        float4 v = h14[(size_t)r * 17 + lane];  // one LDG.128 per lane
        a.x = fmaf(v.x, dr, a.x); a.y = fmaf(v.y, dr, a.y);
        a.z = fmaf(v.z, dr, a.z); a.w = fmaf(v.w, dr, a.w);
    }
    float dc = g_dinv[c];
    {   // self loop
        float4 v = h14[(size_t)c * 17 + lane];
        a.x = fmaf(v.x, dc, a.x); a.y = fmaf(v.y, dc, a.y);
        a.z = fmaf(v.z, dc, a.z); a.w = fmaf(v.w, dc, a.w);
    }

    int cb = lane * 4;
    float4 bv;
    bv.x = b1[cb];
    bv.y = (cb + 1 < HID) ? b1[cb + 1] : 0.f;
    bv.z = (cb + 2 < HID) ? b1[cb + 2] : 0.f;
    bv.w = (cb + 3 < HID) ? b1[cb + 3] : 0.f;

    float4 o;
    o.x = dc * a.x + bv.x;  o.x = o.x > 0.f ? o.x : 0.01f * o.x;
    o.y = dc * a.y + bv.y;  o.y = o.y > 0.f ? o.y : 0.01f * o.y;
    o.z = dc * a.z + bv.z;  o.z = o.z > 0.f ? o.z : 0.01f * o.z;
    o.w = dc * a.w + bv.w;  o.w = o.w > 0.f ? o.w : 0.01f * o.w;
    if (lane == 16) o.w = 0.f;   // keep pad column zero
    reinterpret_cast<float4*>(g_o1)[(size_t)c * 17 + lane] = o;
}

// ---------------- GEMM2: h2 = (o1 @ W2) * dinv[row] (padded in/out) -------------
#define G2_T 128
__global__ void k_gemm2(const float* __restrict__ W2) {
    __shared__ float w2s[HID * CLS];
    __shared__ float os[G2_T][HID + 2];
    int tid = threadIdx.x;
    int row0 = blockIdx.x * G2_T;
    for (int idx = tid; idx < HID * CLS; idx += G2_T) w2s[idx] = W2[idx];
    for (int idx = tid; idx < G2_T * HID; idx += G2_T) {
        int r = idx / HID, k = idx % HID;
        int gr = row0 + r;
        os[r][k] = (gr < NN) ? g_o1[(size_t)gr * H1P + k] : 0.f;
    }
    __syncthreads();
    int gr = row0 + tid;
    if (gr < NN) {
        float acc[CLS];
        #pragma unroll
        for (int j = 0; j < CLS; j++) acc[j] = 0.f;
        for (int k = 0; k < HID; k++) {
            float v = os[tid][k];
            #pragma unroll
            for (int j = 0; j < CLS; j++) acc[j] += v * w2s[k * CLS + j];
        }
        float d = g_dinv[gr];
        #pragma unroll
        for (int j = 0; j < CLS; j++) g_h2[(size_t)gr * H2P + j] = acc[j] * d;
        // col 7 stays 0 (zero-init, never written)
    }
}

// ---------------- Aggregation layer 2 + bias + log_softmax ----------------------
__global__ void k_agg2(const float* __restrict__ b2, float* __restrict__ out) {
    int warp = (blockIdx.x * blockDim.x + threadIdx.x) >> 5;
    int lane = threadIdx.x & 31;
    if (warp >= NN) return;
    int c = warp;
    int s = g_off[c], e = g_off[c + 1];
    float acc[8];
    #pragma unroll
    for (int j = 0; j < 8; j++) acc[j] = 0.f;
    const float4* h24 = reinterpret_cast<const float4*>(g_h2);
    for (int i = s + lane; i < e; i += 32) {
        int r = g_nbr[i];
        float4 lo = h24[(size_t)r * 2];       // 2x LDG.128 per edge-lane
        float4 hi = h24[(size_t)r * 2 + 1];
        acc[0] += lo.x; acc[1] += lo.y; acc[2] += lo.z; acc[3] += lo.w;
        acc[4] += hi.x; acc[5] += hi.y; acc[6] += hi.z; acc[7] += hi.w;
    }
    #pragma unroll
    for (int j = 0; j < CLS; j++) {
        #pragma unroll
        for (int o = 16; o > 0; o >>= 1)
            acc[j] += __shfl_xor_sync(0xffffffffu, acc[j], o);
    }
    if (lane == 0) {
        float d = g_dinv[c];
        const float* hc = g_h2 + (size_t)c * H2P;
        float v[CLS];
        float m = -1e30f;
        #pragma unroll
        for (int j = 0; j < CLS; j++) {
            v[j] = d * (acc[j] + hc[j]) + b2[j];
            m = fmaxf(m, v[j]);
        }
        float sum = 0.f;
        #pragma unroll
        for (int j = 0; j < CLS; j++) sum += __expf(v[j] - m);
        float lse = m + __logf(sum);
        #pragma unroll
        for (int j = 0; j < CLS; j++) out[(size_t)c * CLS + j] = v[j] - lse;
    }
}

// ---------------- launch --------------------------------------------------------
// Fork-join capture: gemm1 (x,W1 only) runs on a side stream concurrently with
// the edge chain (init->count->dinv->scan->scatter). Join before agg1.
// Streams/events are host-side resources (no device memory); created fresh per
// call and intentionally not destroyed (kernel_launch runs only a few times).
extern "C" void kernel_launch(void* const* d_in, const int* in_sizes, int n_in,
                              void* d_out, int out_size) {
    const float* x  = (const float*)d_in[0];
    const int*   ei = (const int*)d_in[1];
    const float* W1 = (const float*)d_in[2];
    const float* b1 = (const float*)d_in[3];
    const float* W2 = (const float*)d_in[4];
    const float* b2 = (const float*)d_in[5];
    float* out = (float*)d_out;
    const int* row = ei;        // edge_index[0]
    const int* col = ei + EE;   // edge_index[1]

    cudaStream_t s2;
    cudaEvent_t evF, evJ;
    cudaStreamCreateWithFlags(&s2, cudaStreamNonBlocking);
    cudaEventCreateWithFlags(&evF, cudaEventDisableTiming);
    cudaEventCreateWithFlags(&evJ, cudaEventDisableTiming);

    // fork: gemm1 on side stream
    cudaEventRecord(evF, 0);
    cudaStreamWaitEvent(s2, evF, 0);
    k_gemm1<<<(NN + G1_M - 1) / G1_M, G1_T, 0, s2>>>(x, W1);
    cudaEventRecord(evJ, s2);

    // edge chain on main stream (concurrent with gemm1)
    k_init<<<(NN + 255) / 256, 256>>>();
    k_count<<<(EE + 255) / 256, 256>>>(col);
    k_dinv<<<(NN + 255) / 256, 256>>>();
    k_scan<<<1, 1024>>>();
    k_scatter<<<(EE + 255) / 256, 256>>>(row, col);

    // join: agg1 needs h1 + CSR + dinv
    cudaStreamWaitEvent(0, evJ, 0);
    {
        long long threads = (long long)NN * 32;
        k_agg1<<<(int)((threads + 255) / 256), 256>>>(b1);
    }
    k_gemm2<<<(NN + G2_T - 1) / G2_T, G2_T>>>(W2);
    {
        long long threads = (long long)NN * 32;
        k_agg2<<<(int)((threads + 255) / 256), 256>>>(b2, out);
    }
}

// round 15
// speedup vs baseline: 4.2230x; 1.0006x over previous
#include <cuda_runtime.h>
#include <cstdint>

#define NN 100000
#define EE 3200000
#define FIN 1433
#define HID 67
#define H1P 68          // padded h1/o1 row stride (16B-aligned, col 67 == 0)
#define CLS 7
#define H2P 8           // padded h2 row stride (32B-aligned, col 7 == 0)

// ---------------- scratch (static device globals; zero-initialized) -------------
__device__ int   g_cnt[NN];
__device__ int   g_off[NN + 1];
__device__ int   g_cur[NN];
__device__ int   g_nbr[EE];
__device__ float g_dinv[NN];
__device__ float g_h1[(size_t)NN * H1P];   // x@W1 (UNscaled), padded
__device__ float g_o1[(size_t)NN * H1P];   // leaky_relu(agg1 + b1), padded
__device__ float g_h2[(size_t)NN * H2P];   // (o1@W2) * dinv[row], padded

// ---------------- degree counting ----------------
__global__ void k_init() {
    int i = blockIdx.x * blockDim.x + threadIdx.x;
    if (i < NN) g_cnt[i] = 0;
}

__global__ void k_count(const int* __restrict__ col) {
    int e = blockIdx.x * blockDim.x + threadIdx.x;
    if (e < EE) atomicAdd(&g_cnt[col[e]], 1);
}

__global__ void k_dinv() {
    int i = blockIdx.x * blockDim.x + threadIdx.x;
    if (i < NN) g_dinv[i] = rsqrtf((float)(g_cnt[i] + 1));  // +1 self loop
}

// ---------------- exclusive scan of g_cnt -> g_off, g_cur (single block) --------
__global__ void k_scan() {
    __shared__ int wsum[32];
    __shared__ int carry_s;
    int tid = threadIdx.x, lane = tid & 31, wid = tid >> 5;
    if (tid == 0) carry_s = 0;
    __syncthreads();
    for (int base = 0; base < NN; base += 1024) {
        int i = base + tid;
        int v = (i < NN) ? g_cnt[i] : 0;
        int x = v;
        #pragma unroll
        for (int o = 1; o < 32; o <<= 1) {
            int y = __shfl_up_sync(0xffffffffu, x, o);
            if (lane >= o) x += y;
        }
        if (lane == 31) wsum[wid] = x;
        __syncthreads();
        if (wid == 0) {
            int s = wsum[lane];
            #pragma unroll
            for (int o = 1; o < 32; o <<= 1) {
                int y = __shfl_up_sync(0xffffffffu, s, o);
                if (lane >= o) s += y;
            }
            wsum[lane] = s;
        }
        __syncthreads();
        int carry = carry_s;
        int exc = x - v + (wid > 0 ? wsum[wid - 1] : 0);
        if (i < NN) { g_off[i] = carry + exc; g_cur[i] = carry + exc; }
        int tot = wsum[31];
        __syncthreads();
        if (tid == 0) carry_s = carry + tot;
        __syncthreads();
    }
    if (tid == 0) g_off[NN] = carry_s;  // == EE
}

// ---------------- CSR scatter ----------------------------------------------------
__global__ void k_scatter(const int* __restrict__ row, const int* __restrict__ col) {
    int e = blockIdx.x * blockDim.x + threadIdx.x;
    if (e < EE) {
        int c = col[e];
        int p = atomicAdd(&g_cur[c], 1);
        g_nbr[p] = row[e];
    }
}

// ---------------- GEMM1 (warp-MMA tf32, direct-A): h1 = x @ W1 (unscaled) -------
// Depends ONLY on x, W1 -> runs on a forked stream concurrently with the
// edge-processing chain. dinv folded into agg1.
#define G1_T     256
#define G1_M     128
#define G1_KC    16
#define G1_NF    89            // full chunks (k < 1424)
#define G1_NCH   90
#define BSTR     26
#define BBUF     (72 * BSTR)

__device__ __forceinline__ uint32_t tf32(float v) {
    uint32_t u;
    asm("cvt.rna.tf32.f32 %0, %1;" : "=r"(u) : "f"(v));
    return u;
}

__device__ __forceinline__ void mma_tf32(float* d, const uint32_t* a,
                                         uint32_t b0, uint32_t b1) {
    asm volatile(
        "mma.sync.aligned.m16n8k8.row.col.f32.tf32.tf32.f32 "
        "{%0,%1,%2,%3}, {%4,%5,%6,%7}, {%8,%9}, {%0,%1,%2,%3};"
        : "+f"(d[0]), "+f"(d[1]), "+f"(d[2]), "+f"(d[3])
        : "r"(a[0]), "r"(a[1]), "r"(a[2]), "r"(a[3]), "r"(b0), "r"(b1));
}

__global__ __launch_bounds__(G1_T, 3) void k_gemm1(const float* __restrict__ x,
                                                   const float* __restrict__ W1) {
    __shared__ __align__(16) float Bs[2][BBUF];
    const int il[8] = {0, 2, 4, 6, 1, 3, 5, 7};
    int tid = threadIdx.x;
    int lane = tid & 31, w = tid >> 5;
    int g = lane >> 2, t = lane & 3;
    int row0 = blockIdx.x * G1_M + w * 16;

    int rg0 = min(row0 + g, NN - 1);
    int rg8 = min(row0 + 8 + g, NN - 1);
    const float* pA0 = x + (size_t)rg0 * FIN + t;
    const float* pA1 = x + (size_t)rg8 * FIN + t;

    bool bstage = tid < 144;
    int bn = tid % 72;
    int bk0 = (tid / 72) * 8;
    bool bnok = bn < HID;
    const float* pB = W1 + bk0 * HID + bn;
    int bsts = bn * BSTR + bk0;   // word offset in Bs buffer

    float acc[9][4];
    #pragma unroll
    for (int nt = 0; nt < 9; nt++)
        #pragma unroll
        for (int q = 0; q < 4; q++) acc[nt][q] = 0.f;

    float pc[8], pn[8], pw[8];

    // ---- chunk 0: load A regs + stage B buffer 0 ----
    #pragma unroll
    for (int j = 0; j < 4; j++) { pc[j] = pA0[4 * j]; pc[4 + j] = pA1[4 * j]; }
    pA0 += G1_KC; pA1 += G1_KC;
    if (bstage) {
        #pragma unroll
        for (int j = 0; j < 8; j++) pw[j] = bnok ? pB[j * HID] : 0.f;
        #pragma unroll
        for (int j = 0; j < 8; j++)
            Bs[0][bsts + il[j]] = __uint_as_float(tf32(pw[j]));
    }
    pB += G1_KC * HID;
    __syncthreads();

    for (int c = 0; c < G1_NCH; c++) {
        int buf = c & 1;

        // prefetch chunk c+1
        if (c + 1 < G1_NCH) {
            if (c + 1 < G1_NF) {        // fully in-bounds, zero predicates
                #pragma unroll
                for (int j = 0; j < 4; j++) { pn[j] = pA0[4 * j]; pn[4 + j] = pA1[4 * j]; }
                if (bstage) {
                    #pragma unroll
                    for (int j = 0; j < 8; j++) pw[j] = bnok ? pB[j * HID] : 0.f;
                }
            } else {                     // chunk 89: clamp A cols, zero B OOB rows
                #pragma unroll
                for (int j = 0; j < 4; j++) {
                    int off = min(4 * j, 8 - t);   // keeps col <= 1432
                    pn[j] = pA0[off]; pn[4 + j] = pA1[off];
                }
                if (bstage) {
                    #pragma unroll
                    for (int j = 0; j < 8; j++) {
                        int k = G1_NF * G1_KC + bk0 + j;
                        pw[j] = (bnok && k < FIN) ? pB[j * HID] : 0.f;
                    }
                }
            }
            pA0 += G1_KC; pA1 += G1_KC; pB += G1_KC * HID;
        }

        // compute chunk c: A from regs, B from Bs[buf]
        #pragma unroll
        for (int s = 0; s < 2; s++) {
            uint32_t af[4];
            af[0] = __float_as_uint(pc[2 * s + 0]);
            af[1] = __float_as_uint(pc[2 * s + 4]);
            af[2] = __float_as_uint(pc[2 * s + 1]);
            af[3] = __float_as_uint(pc[2 * s + 5]);
            const float* bb = &Bs[buf][g * BSTR + s * 8 + 2 * t];
            #pragma unroll
            for (int nt = 0; nt < 9; nt++) {
                float blo = bb[nt * 8 * BSTR];
                float bhi = bb[nt * 8 * BSTR + 1];
                mma_tf32(acc[nt], af, __float_as_uint(blo), __float_as_uint(bhi));
            }
        }

        if (c + 1 < G1_NCH) {
            if (bstage) {
                #pragma unroll
                for (int j = 0; j < 8; j++)
                    Bs[buf ^ 1][bsts + il[j]] = __uint_as_float(tf32(pw[j]));
            }
            __syncthreads();
            #pragma unroll
            for (int j = 0; j < 8; j++) pc[j] = pn[j];
        }
    }

    // epilogue: store RAW acc (padded stride H1P; col 67 never written -> 0)
    int r0 = row0 + g;
    int r1 = r0 + 8;
    #pragma unroll
    for (int nt = 0; nt < 9; nt++) {
        int col = nt * 8 + 2 * t;
        if (col < HID) {
            if (r0 < NN) g_h1[(size_t)r0 * H1P + col] = acc[nt][0];
            if (r1 < NN) g_h1[(size_t)r1 * H1P + col] = acc[nt][2];
        }
        if (col + 1 < HID) {
            if (r0 < NN) g_h1[(size_t)r0 * H1P + col + 1] = acc[nt][1];
            if (r1 < NN) g_h1[(size_t)r1 * H1P + col + 1] = acc[nt][3];
        }
    }
}

// ---------------- Aggregation layer 1 (warp/node; lanes 0..16 x float4) ---------
// h1 is UNscaled; scale each neighbor by dinv[r] here (fma), self by dinv[c].
__global__ void k_agg1(const float* __restrict__ b1) {
    int warp = (blockIdx.x * blockDim.x + threadIdx.x) >> 5;
    int lane = threadIdx.x & 31;
    if (warp >= NN || lane >= 17) return;
    int c = warp;
    int s = g_off[c], e = g_off[c + 1];

    float4 a = make_float4(0.f, 0.f, 0.f, 0.f);
    const float4* h14 = reinterpret_cast<const float4*>(g_h1);
    for (int i = s; i < e; i++) {
        int r = g_nbr[i];                       // uniform across active lanes
        float dr = g_dinv[r];
        float4 v = h14[(size_t)r * 17 + lane];  // one LDG.128 per lane
        a.x = fmaf(v.x, dr, a.x); a.y = fmaf(v.y, dr, a.y);
        a.z = fmaf(v.z, dr, a.z); a.w = fmaf(v.w, dr, a.w);
    }
    float dc = g_dinv[c];
    {   // self loop
        float4 v = h14[(size_t)c * 17 + lane];
        a.x = fmaf(v.x, dc, a.x); a.y = fmaf(v.y, dc, a.y);
        a.z = fmaf(v.z, dc, a.z); a.w = fmaf(v.w, dc, a.w);
    }

    int cb = lane * 4;
    float4 bv;
    bv.x = b1[cb];
    bv.y = (cb + 1 < HID) ? b1[cb + 1] : 0.f;
    bv.z = (cb + 2 < HID) ? b1[cb + 2] : 0.f;
    bv.w = (cb + 3 < HID) ? b1[cb + 3] : 0.f;

    float4 o;
    o.x = dc * a.x + bv.x;  o.x = o.x > 0.f ? o.x : 0.01f * o.x;
    o.y = dc * a.y + bv.y;  o.y = o.y > 0.f ? o.y : 0.01f * o.y;
    o.z = dc * a.z + bv.z;  o.z = o.z > 0.f ? o.z : 0.01f * o.z;
    o.w = dc * a.w + bv.w;  o.w = o.w > 0.f ? o.w : 0.01f * o.w;
    if (lane == 16) o.w = 0.f;   // keep pad column zero
    reinterpret_cast<float4*>(g_o1)[(size_t)c * 17 + lane] = o;
}

// ---------------- GEMM2: h2 = (o1 @ W2) * dinv[row] (padded in/out) -------------
#define G2_T 128
__global__ void k_gemm2(const float* __restrict__ W2) {
    __shared__ float w2s[HID * CLS];
    __shared__ float os[G2_T][HID + 2];
    int tid = threadIdx.x;
    int row0 = blockIdx.x * G2_T;
    for (int idx = tid; idx < HID * CLS; idx += G2_T) w2s[idx] = W2[idx];
    for (int idx = tid; idx < G2_T * HID; idx += G2_T) {
        int r = idx / HID, k = idx % HID;
        int gr = row0 + r;
        os[r][k] = (gr < NN) ? g_o1[(size_t)gr * H1P + k] : 0.f;
    }
    __syncthreads();
    int gr = row0 + tid;
    if (gr < NN) {
        float acc[CLS];
        #pragma unroll
        for (int j = 0; j < CLS; j++) acc[j] = 0.f;
        for (int k = 0; k < HID; k++) {
            float v = os[tid][k];
            #pragma unroll
            for (int j = 0; j < CLS; j++) acc[j] += v * w2s[k * CLS + j];
        }
        float d = g_dinv[gr];
        #pragma unroll
        for (int j = 0; j < CLS; j++) g_h2[(size_t)gr * H2P + j] = acc[j] * d;
        // col 7 stays 0 (zero-init, never written)
    }
}

// ---------------- Aggregation layer 2 + bias + log_softmax ----------------------
__global__ void k_agg2(const float* __restrict__ b2, float* __restrict__ out) {
    int warp = (blockIdx.x * blockDim.x + threadIdx.x) >> 5;
    int lane = threadIdx.x & 31;
    if (warp >= NN) return;
    int c = warp;
    int s = g_off[c], e = g_off[c + 1];
    float acc[8];
    #pragma unroll
    for (int j = 0; j < 8; j++) acc[j] = 0.f;
    const float4* h24 = reinterpret_cast<const float4*>(g_h2);
    for (int i = s + lane; i < e; i += 32) {
        int r = g_nbr[i];
        float4 lo = h24[(size_t)r * 2];       // 2x LDG.128 per edge-lane
        float4 hi = h24[(size_t)r * 2 + 1];
        acc[0] += lo.x; acc[1] += lo.y; acc[2] += lo.z; acc[3] += lo.w;
        acc[4] += hi.x; acc[5] += hi.y; acc[6] += hi.z; acc[7] += hi.w;
    }
    #pragma unroll
    for (int j = 0; j < CLS; j++) {
        #pragma unroll
        for (int o = 16; o > 0; o >>= 1)
            acc[j] += __shfl_xor_sync(0xffffffffu, acc[j], o);
    }
    if (lane == 0) {
        float d = g_dinv[c];
        const float* hc = g_h2 + (size_t)c * H2P;
        float v[CLS];
        float m = -1e30f;
        #pragma unroll
        for (int j = 0; j < CLS; j++) {
            v[j] = d * (acc[j] + hc[j]) + b2[j];
            m = fmaxf(m, v[j]);
        }
        float sum = 0.f;
        #pragma unroll
        for (int j = 0; j < CLS; j++) sum += __expf(v[j] - m);
        float lse = m + __logf(sum);
        #pragma unroll
        for (int j = 0; j < CLS; j++) out[(size_t)c * CLS + j] = v[j] - lse;
    }
}

// ---------------- launch --------------------------------------------------------
// Fork-join capture: gemm1 (x,W1 only) runs on a side stream concurrently with
// the edge chain (init->count->dinv->scan->scatter). Join before agg1.
// Streams/events are host-side resources (no device memory); created fresh per
// call and intentionally not destroyed (kernel_launch runs only a few times).
extern "C" void kernel_launch(void* const* d_in, const int* in_sizes, int n_in,
                              void* d_out, int out_size) {
    const float* x  = (const float*)d_in[0];
    const int*   ei = (const int*)d_in[1];
    const float* W1 = (const float*)d_in[2];
    const float* b1 = (const float*)d_in[3];
    const float* W2 = (const float*)d_in[4];
    const float* b2 = (const float*)d_in[5];
    float* out = (float*)d_out;
    const int* row = ei;        // edge_index[0]
    const int* col = ei + EE;   // edge_index[1]

    cudaStream_t s2;
    cudaEvent_t evF, evJ;
    cudaStreamCreateWithFlags(&s2, cudaStreamNonBlocking);
    cudaEventCreateWithFlags(&evF, cudaEventDisableTiming);
    cudaEventCreateWithFlags(&evJ, cudaEventDisableTiming);

    // fork: gemm1 on side stream
    cudaEventRecord(evF, 0);
    cudaStreamWaitEvent(s2, evF, 0);
    k_gemm1<<<(NN + G1_M - 1) / G1_M, G1_T, 0, s2>>>(x, W1);
    cudaEventRecord(evJ, s2);

    // edge chain on main stream (concurrent with gemm1)
    k_init<<<(NN + 255) / 256, 256>>>();
    k_count<<<(EE + 255) / 256, 256>>>(col);
    k_dinv<<<(NN + 255) / 256, 256>>>();
    k_scan<<<1, 1024>>>();
    k_scatter<<<(EE + 255) / 256, 256>>>(row, col);

    // join: agg1 needs h1 + CSR + dinv
    cudaStreamWaitEvent(0, evJ, 0);
    {
        long long threads = (long long)NN * 32;
        k_agg1<<<(int)((threads + 255) / 256), 256>>>(b1);
    }
    k_gemm2<<<(NN + G2_T - 1) / G2_T, G2_T>>>(W2);
    {
        long long threads = (long long)NN * 32;
        k_agg2<<<(int)((threads + 255) / 256), 256>>>(b2, out);
    }
}